// round 7
// baseline (speedup 1.0000x reference)
#include <cuda_runtime.h>
#include <math.h>

// ---------------- packed f32x2 FMA (sm_103a FFMA2) ----------------
__device__ __forceinline__ void fma2(unsigned long long& d,
                                     unsigned long long a, unsigned long long b) {
    asm("fma.rn.f32x2 %0, %1, %2, %3;" : "=l"(d) : "l"(a), "l"(b), "l"(d));
}
__device__ __forceinline__ float pairsum(unsigned long long v) {
    return __uint_as_float((unsigned)v) + __uint_as_float((unsigned)(v >> 32));
}

// ---------------- scratch (device globals; no mallocs) ----------------
// g_c1 rows padded 28 -> 36 floats so conv2 can do unconditional vector loads.
__device__ __align__(16) float g_c1[2048*32*28*36];   // conv1 out (padded rows)
__device__ __align__(16) float g_c2[2048*64*13*13];   // conv2 out
__device__ __align__(16) float g_c3[2048*64*36];      // conv3 out (N,64,36)
__device__ float g_catt[2048*64];       // channel attention
__device__ __align__(16) float g_tok[2048*36*64];     // tokens (N,36,64)
__device__ __align__(16) float g_qkv[2048*36*192];    // qkv
__device__ __align__(16) float g_attn[2048*36*64];    // attention out
__device__ __align__(16) float g_h2[2048*2304];       // residual -> FC input
__device__ __align__(16) float g_feat[2048*256];      // FC out
__device__ __align__(16) float g_gx[2048*384];        // input-side GRU gates
__device__ __align__(16) float g_hid[2048*128];       // GRU hidden per step
__device__ __align__(16) float g_w1p[256*32];         // conv1 w, kx-paired: [(cin,ky,kxp)][co][2]
__device__ __align__(16) float g_w2p[512*64];         // conv2 w, kx-paired
__device__ __align__(16) float g_w3t[576*64];         // conv3 w transposed [k][cout]
__device__ __align__(16) float g_whht[128*384];       // whh transposed [k][gate]

// ---------------- weight prep ----------------
// conv1 (32,4,8,8): dst[((cin*8+ky)*4+kx/2)*64 + co*2 + (kx&1)]
__global__ void k_pack1(const float* __restrict__ w) {
    int idx = blockIdx.x*256 + threadIdx.x;
    if (idx >= 8192) return;
    int co = idx >> 8, k = idx & 255;     // k = cin*64+ky*8+kx
    int kx = k & 7, ck = k >> 3;          // ck = cin*8+ky
    g_w1p[(ck*4 + (kx>>1))*64 + co*2 + (kx&1)] = w[idx];
}
// conv2 (64,32,4,4): dst[((cin*4+ky)*2+kx/2)*128 + co*2 + (kx&1)]
__global__ void k_pack2(const float* __restrict__ w) {
    int idx = blockIdx.x*256 + threadIdx.x;
    if (idx >= 32768) return;
    int co = idx >> 9, k = idx & 511;     // k = cin*16+ky*4+kx
    int kx = k & 3, ck = k >> 2;          // ck = cin*4+ky
    g_w2p[(ck*2 + (kx>>1))*128 + co*2 + (kx&1)] = w[idx];
}
__global__ void k_transpose(const float* __restrict__ w, int Cout, int K, int which) {
    int idx = blockIdx.x*256 + threadIdx.x;
    if (idx >= Cout*K) return;
    int co = idx / K, k = idx % K;
    float* dst = (which==2) ? g_w3t : g_whht;
    dst[k*Cout + co] = w[idx];
}

// ---------------- conv1: (N,4,116,116) -> relu (N,32,28,28pad36), k8 s4 --------
// grid(7, 2048), block 256 (8 warps = 4 oy rows; 2 warps per row cover 28 ox).
// Warp lane = cq(16) + 16*oxq(2); thread: 7 ox x 2 cout, kx even/odd packed.
// Per (cin,ky): 56 FMA2 (112 MAC) + 4 LDS.128 (weights, broadcast) + 8 LDG.128.
__global__ void __launch_bounds__(256) k_conv1(const float* __restrict__ x,
                                               const float* __restrict__ bias) {
    __shared__ __align__(16) float ws[8192];     // 32 KB packed weights
    for (int i = threadIdx.x; i < 2048; i += 256)
        ((float4*)ws)[i] = ((const float4*)g_w1p)[i];
    __syncthreads();
    int n    = blockIdx.y;
    int w    = threadIdx.x >> 5, lane = threadIdx.x & 31;
    int oy   = blockIdx.x*4 + (w >> 1);
    int cq   = lane & 15;                          // couts 2cq, 2cq+1
    int oxb  = (w & 1)*14 + (lane >> 4)*7;         // 0,7,14,21
    unsigned long long acc[7][2] = {};
    for (int cin = 0; cin < 4; cin++) {
        const float* xin = x + (size_t)(n*4+cin)*13456 + 4*oy*116 + 4*oxb;
        #pragma unroll
        for (int ky = 0; ky < 8; ky++) {
            const float* xr = xin + ky*116;        // 16B-aligned
            unsigned long long xv[16];
            #pragma unroll
            for (int u = 0; u < 8; u++) {
                ulonglong2 v = *(const ulonglong2*)(xr + 4*u);
                xv[2*u] = v.x; xv[2*u+1] = v.y;
            }
            const float* wp = ws + ((cin*8+ky)*4)*64 + 4*cq;
            #pragma unroll
            for (int kxp = 0; kxp < 4; kxp++) {
                ulonglong2 wv = *(const ulonglong2*)(wp + kxp*64);
                #pragma unroll
                for (int i = 0; i < 7; i++) {
                    fma2(acc[i][0], xv[2*i+kxp], wv.x);
                    fma2(acc[i][1], xv[2*i+kxp], wv.y);
                }
            }
        }
    }
    #pragma unroll
    for (int j = 0; j < 2; j++) {
        int co = 2*cq + j;
        float b = bias[co];
        #pragma unroll
        for (int i = 0; i < 7; i++) {
            float r = pairsum(acc[i][j]) + b;
            g_c1[((size_t)(n*32+co)*28 + oy)*36 + oxb + i] = r > 0.f ? r : 0.f;
        }
    }
}

// ---------------- conv2: (N,32,28pad36) -> relu (N,64,13,13), k4 s2 ------------
// grid(7, 2048), block 128 (4 warps; oy>=13 retires early — no barriers, safe).
// Warp lane = cq(32); thread: 7 ox x 2 cout (ox=13 cut), kx even/odd packed.
// Per (cin,ky): 28 FMA2 + 2 weight LDG.128 (L1-hot) + 8 input LD.64 (broadcast).
__global__ void __launch_bounds__(128) k_conv2(const float* __restrict__ bias) {
    int n = blockIdx.y;
    int w = threadIdx.x >> 5, lane = threadIdx.x & 31;
    int oy = blockIdx.x*2 + (w >> 1);
    if (oy >= 13) return;
    int oxb = (w & 1)*7;
    int cq  = lane;                                // couts 2cq, 2cq+1
    unsigned long long acc[7][2] = {};
    for (int cin = 0; cin < 32; cin++) {
        const float* xin = g_c1 + (size_t)(n*32+cin)*1008 + 2*oy*36 + 2*oxb;
        #pragma unroll
        for (int ky = 0; ky < 4; ky++) {
            const float* xr = xin + ky*36;         // 8B-aligned
            unsigned long long xv[8];
            #pragma unroll
            for (int u = 0; u < 8; u++)
                xv[u] = *(const unsigned long long*)(xr + 2*u);
            const float* wp = g_w2p + ((cin*4+ky)*2)*128 + 4*cq;
            #pragma unroll
            for (int kxp = 0; kxp < 2; kxp++) {
                ulonglong2 wv = *(const ulonglong2*)(wp + kxp*128);
                #pragma unroll
                for (int i = 0; i < 7; i++) {
                    fma2(acc[i][0], xv[i+kxp], wv.x);
                    fma2(acc[i][1], xv[i+kxp], wv.y);
                }
            }
        }
    }
    #pragma unroll
    for (int j = 0; j < 2; j++) {
        int co = 2*cq + j;
        float b = bias[co];
        #pragma unroll
        for (int i = 0; i < 7; i++) {
            int ox = oxb + i;
            if (ox < 13) {
                float r = pairsum(acc[i][j]) + b;
                g_c2[((size_t)(n*64+co)*13 + oy)*13 + ox] = r > 0.f ? r : 0.f;
            }
        }
    }
}

// ---------------- conv3: (N,64,13,13) -> relu (N,64,6,6), k3 s2 ----------------
__global__ void k_conv3(const float* __restrict__ bias) {
    __shared__ float xs[64*169];   // 43.3 KB
    int n = blockIdx.x;
    int t = threadIdx.x;
    {
        const float4* src = (const float4*)(g_c2 + (size_t)n*10816);
        float4* dst = (float4*)xs;
        for (int i = t; i < 2704; i += 288) dst[i] = src[i];
    }
    __syncthreads();
    int sq = t % 18, cq = t / 18;    // cq 0..15
    int s0 = sq*2;
    int sy = s0/6, sx = s0%6;
    float acc[2][4] = {};
    for (int cin = 0; cin < 64; cin++) {
        const float* xc = xs + cin*169;
        #pragma unroll
        for (int ky = 0; ky < 3; ky++) {
            const float* row = xc + (2*sy+ky)*13 + 2*sx;
            #pragma unroll
            for (int kx = 0; kx < 3; kx++) {
                float4 wv = *(const float4*)(g_w3t + ((cin*3+ky)*3+kx)*64 + 4*cq);
                float i0 = row[kx];
                float i1 = row[kx+2];
                acc[0][0] += i0*wv.x; acc[0][1] += i0*wv.y;
                acc[0][2] += i0*wv.z; acc[0][3] += i0*wv.w;
                acc[1][0] += i1*wv.x; acc[1][1] += i1*wv.y;
                acc[1][2] += i1*wv.z; acc[1][3] += i1*wv.w;
            }
        }
    }
    #pragma unroll
    for (int j = 0; j < 4; j++) {
        int co = cq*4 + j;
        float b = bias[co];
        #pragma unroll
        for (int i = 0; i < 2; i++) {
            float v = acc[i][j] + b;
            g_c3[(size_t)(n*64+co)*36 + s0 + i] = v > 0.f ? v : 0.f;
        }
    }
}

// ---------------- CBAM channel attention ----------------
__global__ void k_chatt(const float* __restrict__ fc1w, const float* __restrict__ fc2w) {
    __shared__ float pm[64], px[64], hsh[32];
    int n = blockIdx.x, c = threadIdx.x;
    const float* p = g_c3 + (size_t)(n*64+c)*36;
    float sum = 0.f, mx = -1e30f;
    #pragma unroll
    for (int s = 0; s < 36; s++) { float v = p[s]; sum += v; mx = fmaxf(mx, v); }
    pm[c] = sum * (1.f/36.f); px[c] = mx;
    __syncthreads();
    if (c < 32) {
        int k = c & 15;
        const float* src = (c < 16) ? pm : px;
        float a = 0.f;
        #pragma unroll
        for (int j = 0; j < 64; j++) a += fc1w[k*64+j]*src[j];
        hsh[c] = fmaxf(a, 0.f);
    }
    __syncthreads();
    float a = 0.f;
    #pragma unroll
    for (int k = 0; k < 16; k++) a += fc2w[c*16+k]*(hsh[k] + hsh[16+k]);
    g_catt[n*64+c] = 1.f/(1.f+expf(-a));
}

// ---------------- CBAM spatial attention + write tokens (N,36,64) ----------------
__global__ void k_spatial(const float* __restrict__ spw) {
    __shared__ float sh[2304], m2[36], x2[36], ss[36];
    int n = blockIdx.x, t = threadIdx.x;
    for (int o = t; o < 2304; o += 256)
        sh[o] = g_c3[(size_t)n*2304 + o] * g_catt[n*64 + o/36];
    __syncthreads();
    if (t < 36) {
        float sum = 0.f, mx = -1e30f;
        #pragma unroll
        for (int c = 0; c < 64; c++) { float v = sh[c*36+t]; sum += v; mx = fmaxf(mx, v); }
        m2[t] = sum*(1.f/64.f); x2[t] = mx;
    }
    __syncthreads();
    if (t < 36) {
        int sy = t/6, sx = t%6;
        float a = 0.f;
        for (int ky = 0; ky < 7; ky++) {
            int iy = sy + ky - 3; if (iy < 0 || iy >= 6) continue;
            for (int kx = 0; kx < 7; kx++) {
                int ix = sx + kx - 3; if (ix < 0 || ix >= 6) continue;
                a += spw[ky*7+kx]*m2[iy*6+ix] + spw[49+ky*7+kx]*x2[iy*6+ix];
            }
        }
        ss[t] = 1.f/(1.f+expf(-a));
    }
    __syncthreads();
    for (int o = t; o < 2304; o += 256) {
        int c = o/36, s = o%36;
        g_tok[((size_t)n*36 + s)*64 + c] = sh[o]*ss[s];
    }
}

// ---------------- generic SGEMM: C(M,N) = act(A(M,K) @ W(N,K)^T + bias) ----------------
template<int RELU, int BIAS>
__global__ void k_gemm(const float* __restrict__ A, const float* __restrict__ W,
                       const float* __restrict__ bias, float* __restrict__ C,
                       int M, int N, int K) {
    __shared__ float As[16][64], Ws[16][64];
    int m0 = blockIdx.x*64, n0 = blockIdx.y*64;
    int tid = threadIdx.x;
    int lr = tid >> 2, lk = (tid & 3) << 2;
    int tx = tid & 15, ty = tid >> 4;
    float acc[4][4] = {};
    for (int k0 = 0; k0 < K; k0 += 16) {
        float4 a = *(const float4*)(A + (size_t)(m0+lr)*K + k0 + lk);
        float4 w = *(const float4*)(W + (size_t)(n0+lr)*K + k0 + lk);
        As[lk  ][lr] = a.x; As[lk+1][lr] = a.y; As[lk+2][lr] = a.z; As[lk+3][lr] = a.w;
        Ws[lk  ][lr] = w.x; Ws[lk+1][lr] = w.y; Ws[lk+2][lr] = w.z; Ws[lk+3][lr] = w.w;
        __syncthreads();
        #pragma unroll
        for (int kk = 0; kk < 16; kk++) {
            float4 av = *(const float4*)&As[kk][tx<<2];
            float4 wv = *(const float4*)&Ws[kk][ty<<2];
            float ar[4] = {av.x, av.y, av.z, av.w};
            float wr[4] = {wv.x, wv.y, wv.z, wv.w};
            #pragma unroll
            for (int i = 0; i < 4; i++)
                #pragma unroll
                for (int j = 0; j < 4; j++)
                    acc[i][j] += ar[i]*wr[j];
        }
        __syncthreads();
    }
    #pragma unroll
    for (int i = 0; i < 4; i++) {
        int m = m0 + (tx<<2) + i;
        #pragma unroll
        for (int j = 0; j < 4; j++) {
            int nn = n0 + (ty<<2) + j;
            float v = acc[i][j];
            if (BIAS) v += bias[nn];
            if (RELU) v = fmaxf(v, 0.f);
            C[(size_t)m*N + nn] = v;
        }
    }
}

// ---------------- per-(n,head) attention over 36 tokens ----------------
__global__ void k_attn() {
    int head = blockIdx.x, n = blockIdx.y, t = threadIdx.x;
    __shared__ float qs[36*16], ks[36*16], vs[36*16];
    for (int idx = t; idx < 576; idx += 64) {
        int s = idx >> 4, d = idx & 15;
        const float* base = g_qkv + ((size_t)n*36 + s)*192 + head*16 + d;
        qs[idx] = base[0]; ks[idx] = base[64]; vs[idx] = base[128];
    }
    __syncthreads();
    if (t < 36) {
        float qr[16];
        #pragma unroll
        for (int d = 0; d < 16; d++) qr[d] = qs[t*16+d];
        float sc[36]; float mx = -1e30f;
        #pragma unroll
        for (int s2 = 0; s2 < 36; s2++) {
            float a = 0.f;
            #pragma unroll
            for (int d = 0; d < 16; d++) a += qr[d]*ks[s2*16+d];
            a *= 0.25f;
            sc[s2] = a; mx = fmaxf(mx, a);
        }
        float sum = 0.f;
        #pragma unroll
        for (int s2 = 0; s2 < 36; s2++) { float e = expf(sc[s2]-mx); sc[s2] = e; sum += e; }
        float inv = 1.f/sum;
        #pragma unroll
        for (int d = 0; d < 16; d++) {
            float o = 0.f;
            #pragma unroll
            for (int s2 = 0; s2 < 36; s2++) o += sc[s2]*vs[s2*16+d];
            g_attn[((size_t)n*36 + t)*64 + head*16 + d] = o*inv;
        }
    }
}

// ---------------- proj + residual, writes (N,64,36) layout for FC ----------------
__global__ void k_proj(const float* __restrict__ projw, const float* __restrict__ projb) {
    __shared__ float at[2304];
    int n = blockIdx.x, t = threadIdx.x;
    for (int o = t; o < 2304; o += 256) at[o] = g_attn[(size_t)n*2304 + o];
    __syncthreads();
    for (int o = t; o < 2304; o += 256) {
        int c = o/36, s = o%36;
        const float4* pw = (const float4*)(projw + c*64);
        const float4* av = (const float4*)(at + s*64);
        float a = 0.f;
        #pragma unroll
        for (int j = 0; j < 16; j++) {
            float4 p = pw[j], q = av[j];
            a += p.x*q.x + p.y*q.y + p.z*q.z + p.w*q.w;
        }
        g_h2[(size_t)n*2304 + o] = g_tok[((size_t)n*36 + s)*64 + c] + a + projb[c];
    }
}

// ---------------- masked GRU scan: 32 independent batch chains ----------------
__global__ void k_gru(const float* __restrict__ done, const float* __restrict__ h0,
                      const float* __restrict__ bhh) {
    int b = blockIdx.x, t = threadIdx.x;
    __shared__ float h_s[128], hm_s[128], gh_s[384];
    h_s[t] = h0[b*128 + t];
    __syncthreads();
    for (int step = 0; step < 64; step++) {
        float dt = done[step*32 + b];
        hm_s[t] = (1.f - dt)*h_s[t];
        __syncthreads();
        if (t < 96) {
            int g = t*4;
            float a0 = bhh[g], a1 = bhh[g+1], a2 = bhh[g+2], a3 = bhh[g+3];
            #pragma unroll 8
            for (int k = 0; k < 128; k++) {
                float hm = hm_s[k];
                float4 w = *(const float4*)(g_whht + k*384 + g);
                a0 += w.x*hm; a1 += w.y*hm; a2 += w.z*hm; a3 += w.w*hm;
            }
            gh_s[g] = a0; gh_s[g+1] = a1; gh_s[g+2] = a2; gh_s[g+3] = a3;
        }
        __syncthreads();
        int row = step*32 + b;
        float xr = g_gx[(size_t)row*384 + t];
        float xz = g_gx[(size_t)row*384 + 128 + t];
        float xn = g_gx[(size_t)row*384 + 256 + t];
        float hr = gh_s[t], hz = gh_s[128+t], hn = gh_s[256+t];
        float rg = 1.f/(1.f+expf(-(xr+hr)));
        float zg = 1.f/(1.f+expf(-(xz+hz)));
        float ng = tanhf(xn + rg*hn);
        float hnew = (1.f-zg)*ng + zg*hm_s[t];
        h_s[t] = hnew;
        g_hid[(size_t)row*128 + t] = hnew;
        __syncthreads();
    }
}

// ---------------- critic head: (2048,128) @ crw^T + crb ----------------
__global__ void k_critic(const float* __restrict__ crw, const float* __restrict__ crb,
                         float* __restrict__ out) {
    int warp = threadIdx.x >> 5, lane = threadIdx.x & 31;
    int row = blockIdx.x*8 + warp;
    const float4* h4 = (const float4*)(g_hid + (size_t)row*128);
    float4 hv = h4[lane];
    float4 wv = ((const float4*)crw)[lane];
    float s = hv.x*wv.x + hv.y*wv.y + hv.z*wv.z + hv.w*wv.w;
    #pragma unroll
    for (int o = 16; o; o >>= 1) s += __shfl_down_sync(0xffffffffu, s, o);
    if (lane == 0) out[row] = s + crb[0];
}

// ---------------- launch ----------------
extern "C" void kernel_launch(void* const* d_in, const int* in_sizes, int n_in,
                              void* d_out, int out_size) {
    const float* x    = (const float*)d_in[0];
    const float* done = (const float*)d_in[1];
    const float* gru0 = (const float*)d_in[2];
    const float* c1w  = (const float*)d_in[3];
    const float* c1b  = (const float*)d_in[4];
    const float* c2w  = (const float*)d_in[5];
    const float* c2b  = (const float*)d_in[6];
    const float* c3w  = (const float*)d_in[7];
    const float* c3b  = (const float*)d_in[8];
    const float* fc1w = (const float*)d_in[9];
    const float* fc2w = (const float*)d_in[10];
    const float* spw  = (const float*)d_in[11];
    const float* qkvw = (const float*)d_in[12];
    const float* projw= (const float*)d_in[13];
    const float* projb= (const float*)d_in[14];
    const float* fcw  = (const float*)d_in[15];
    const float* fcb  = (const float*)d_in[16];
    const float* wih  = (const float*)d_in[17];
    const float* whh  = (const float*)d_in[18];
    const float* bih  = (const float*)d_in[19];
    const float* bhh  = (const float*)d_in[20];
    const float* crw  = (const float*)d_in[21];
    const float* crb  = (const float*)d_in[22];
    float* out = (float*)d_out;

    float *p_tok, *p_qkv, *p_h2, *p_feat, *p_gx;
    cudaGetSymbolAddress((void**)&p_tok,  g_tok);
    cudaGetSymbolAddress((void**)&p_qkv,  g_qkv);
    cudaGetSymbolAddress((void**)&p_h2,   g_h2);
    cudaGetSymbolAddress((void**)&p_feat, g_feat);
    cudaGetSymbolAddress((void**)&p_gx,   g_gx);

    // prep (ordered so the profiled launch lands on k_conv1, same slot as before)
    k_pack1<<<32, 256>>>(c1w);
    k_pack2<<<128, 256>>>(c2w);
    k_transpose<<<(384*128 + 255)/256, 256>>>(whh, 384, 128, 3);

    // conv backbone
    k_conv1<<<dim3(7, 2048), 256>>>(x, c1b);
    k_transpose<<<(64*576 + 255)/256, 256>>>(c3w, 64, 576, 2);
    k_conv2<<<dim3(7, 2048), 128>>>(c2b);
    k_conv3<<<2048, 288>>>(c3b);

    // CBAM
    k_chatt<<<2048, 64>>>(fc1w, fc2w);
    k_spatial<<<2048, 256>>>(spw);

    // spatial self-attention
    k_gemm<0,0><<<dim3(73728/64, 192/64), 256>>>(p_tok, qkvw, (const float*)0, p_qkv, 73728, 192, 64);
    k_attn<<<dim3(4, 2048), 64>>>();
    k_proj<<<2048, 256>>>(projw, projb);

    // FC + GRU input gates
    k_gemm<1,1><<<dim3(2048/64, 256/64), 256>>>(p_h2, fcw, fcb, p_feat, 2048, 256, 2304);
    k_gemm<0,1><<<dim3(2048/64, 384/64), 256>>>(p_feat, wih, bih, p_gx, 2048, 384, 256);

    // GRU scan + critic
    k_gru<<<32, 128>>>(done, gru0, bhh);
    k_critic<<<2048/8, 256>>>(crw, crb, out);
}

// round 8
// speedup vs baseline: 1.3295x; 1.3295x over previous
#include <cuda_runtime.h>
#include <math.h>

// ---------------- scratch (device globals; no mallocs) ----------------
// g_c1 rows padded 28 -> 36 floats so conv2 can do unconditional vector loads.
__device__ __align__(16) float g_c1[2048*32*28*36];   // conv1 out (padded rows)
__device__ __align__(16) float g_c2[2048*64*13*13];   // conv2 out
__device__ __align__(16) float g_c3[2048*64*36];      // conv3 out (N,64,36)
__device__ float g_catt[2048*64];       // channel attention
__device__ __align__(16) float g_tok[2048*36*64];     // tokens (N,36,64)
__device__ __align__(16) float g_qkv[2048*36*192];    // qkv
__device__ __align__(16) float g_attn[2048*36*64];    // attention out (N,36,64)
__device__ __align__(16) float g_h2[2048*2304];       // residual -> FC input
__device__ __align__(16) float g_feat[2048*256];      // FC out
__device__ __align__(16) float g_gx[2048*384];        // input-side GRU gates
__device__ __align__(16) float g_hid[2048*128];       // GRU hidden per step
__device__ __align__(16) float g_w1t[256*32];         // conv weights transposed [k][cout]
__device__ __align__(16) float g_w2t[512*64];
__device__ __align__(16) float g_w3t[576*64];
__device__ __align__(16) float g_whht[128*384];       // whh transposed [k][gate]

// ---------------- weight transpose prep ----------------
__global__ void k_transpose(const float* __restrict__ w, int Cout, int K, int which) {
    int idx = blockIdx.x*256 + threadIdx.x;
    if (idx >= Cout*K) return;
    int co = idx / K, k = idx % K;
    float* dst = (which==0) ? g_w1t : (which==1) ? g_w2t : (which==2) ? g_w3t : g_whht;
    dst[k*Cout + co] = w[idx];
}

// ---------------- conv1: (N,4,116,116) -> relu (N,32,28,28pad36), k8 s4 --------
// grid(7, 2048), block 128 (4 warps = 4 oy rows). Warp = cq(8) x oxq(4);
// thread tile: 7 ox x 4 cout. Per (cin,ky): 224 FFMA vs 8 LDS.128 + 8 LDG.128.
__global__ void __launch_bounds__(128) k_conv1(const float* __restrict__ x,
                                               const float* __restrict__ bias) {
    __shared__ float ws[256*32];     // 32 KB, [k][cout] layout
    for (int i = threadIdx.x; i < 2048; i += 128)
        ((float4*)ws)[i] = ((const float4*)g_w1t)[i];
    __syncthreads();
    int n    = blockIdx.y;
    int oy   = blockIdx.x*4 + threadIdx.x/32;
    int lane = threadIdx.x % 32;
    int cq   = lane % 8;        // cout quad (broadcast-friendly LDS)
    int oxq  = lane / 8;        // 0..3 -> ox0 = 7*oxq
    float acc[7][4] = {};
    for (int cin = 0; cin < 4; cin++) {
        const float* xin = x + (size_t)(n*4+cin)*13456 + 4*oy*116 + 28*oxq;
        #pragma unroll
        for (int ky = 0; ky < 8; ky++) {
            const float* xr = xin + ky*116;
            float xv[32];
            #pragma unroll
            for (int u = 0; u < 8; u++) {
                float4 v = *(const float4*)(xr + 4*u);
                xv[4*u]=v.x; xv[4*u+1]=v.y; xv[4*u+2]=v.z; xv[4*u+3]=v.w;
            }
            const float* wp = ws + ((cin*8+ky)*8)*32 + 4*cq;
            #pragma unroll
            for (int kx = 0; kx < 8; kx++) {
                float4 wv = *(const float4*)(wp + kx*32);
                #pragma unroll
                for (int i = 0; i < 7; i++) {
                    float iv = xv[4*i+kx];
                    acc[i][0] += iv*wv.x; acc[i][1] += iv*wv.y;
                    acc[i][2] += iv*wv.z; acc[i][3] += iv*wv.w;
                }
            }
        }
    }
    #pragma unroll
    for (int j = 0; j < 4; j++) {
        int co = cq*4 + j;
        float b = bias[co];
        #pragma unroll
        for (int i = 0; i < 7; i++) {
            float v = acc[i][j] + b;
            g_c1[((size_t)(n*32+co)*28 + oy)*36 + 7*oxq + i] = v > 0.f ? v : 0.f;
        }
    }
}

// ---------------- conv2: (N,32,28pad36) -> relu (N,64,13,13), k4 s2 ------------
// grid(13, 512), block 128: warp = one (n, oy) pair — zero oy waste.
// Warp = cq(16) x oxq(2); thread tile: 7 ox x 4 cout (ox=13 cut).
// Per (cin,ky): 112 FFMA vs 4 weight LDG.128 (L1-hot) + 8 input LD.64.
__global__ void __launch_bounds__(128) k_conv2(const float* __restrict__ bias) {
    int w = threadIdx.x >> 5, lane = threadIdx.x & 31;
    int n  = blockIdx.y*4 + w;
    int oy = blockIdx.x;
    int cq  = lane % 16;        // 0..15 -> cout quad
    int oxq = lane / 16;        // 0..1 -> ox0 = 7*oxq
    float acc[7][4] = {};
    for (int cin = 0; cin < 32; cin++) {
        const float* xin = g_c1 + (size_t)(n*32+cin)*1008 + 2*oy*36 + 14*oxq;
        #pragma unroll
        for (int ky = 0; ky < 4; ky++) {
            const float* xr = xin + ky*36;         // 8B-aligned
            float xv[16];
            #pragma unroll
            for (int u = 0; u < 8; u++) {
                float2 v = *(const float2*)(xr + 2*u);
                xv[2*u]=v.x; xv[2*u+1]=v.y;
            }
            const float* wp = g_w2t + ((cin*4+ky)*4)*64 + 4*cq;
            #pragma unroll
            for (int kx = 0; kx < 4; kx++) {
                float4 wv = *(const float4*)(wp + kx*64);
                #pragma unroll
                for (int i = 0; i < 7; i++) {
                    float iv = xv[2*i+kx];
                    acc[i][0] += iv*wv.x; acc[i][1] += iv*wv.y;
                    acc[i][2] += iv*wv.z; acc[i][3] += iv*wv.w;
                }
            }
        }
    }
    #pragma unroll
    for (int j = 0; j < 4; j++) {
        int co = cq*4 + j;
        float b = bias[co];
        #pragma unroll
        for (int i = 0; i < 7; i++) {
            int ox = 7*oxq + i;
            if (ox < 13) {
                float v = acc[i][j] + b;
                g_c2[((size_t)(n*64+co)*13 + oy)*13 + ox] = v > 0.f ? v : 0.f;
            }
        }
    }
}

// ---------------- conv3: (N,64,13,13) -> relu (N,64,6,6), k3 s2 ----------------
__global__ void k_conv3(const float* __restrict__ bias) {
    __shared__ float xs[64*169];   // 43.3 KB
    int n = blockIdx.x;
    int t = threadIdx.x;
    {
        const float4* src = (const float4*)(g_c2 + (size_t)n*10816);
        float4* dst = (float4*)xs;
        for (int i = t; i < 2704; i += 288) dst[i] = src[i];
    }
    __syncthreads();
    int sq = t % 18, cq = t / 18;    // cq 0..15
    int s0 = sq*2;
    int sy = s0/6, sx = s0%6;
    float acc[2][4] = {};
    for (int cin = 0; cin < 64; cin++) {
        const float* xc = xs + cin*169;
        #pragma unroll
        for (int ky = 0; ky < 3; ky++) {
            const float* row = xc + (2*sy+ky)*13 + 2*sx;
            #pragma unroll
            for (int kx = 0; kx < 3; kx++) {
                float4 wv = *(const float4*)(g_w3t + ((cin*3+ky)*3+kx)*64 + 4*cq);
                float i0 = row[kx];
                float i1 = row[kx+2];
                acc[0][0] += i0*wv.x; acc[0][1] += i0*wv.y;
                acc[0][2] += i0*wv.z; acc[0][3] += i0*wv.w;
                acc[1][0] += i1*wv.x; acc[1][1] += i1*wv.y;
                acc[1][2] += i1*wv.z; acc[1][3] += i1*wv.w;
            }
        }
    }
    #pragma unroll
    for (int j = 0; j < 4; j++) {
        int co = cq*4 + j;
        float b = bias[co];
        #pragma unroll
        for (int i = 0; i < 2; i++) {
            float v = acc[i][j] + b;
            g_c3[(size_t)(n*64+co)*36 + s0 + i] = v > 0.f ? v : 0.f;
        }
    }
}

// ---------------- CBAM channel attention ----------------
__global__ void k_chatt(const float* __restrict__ fc1w, const float* __restrict__ fc2w) {
    __shared__ float pm[64], px[64], hsh[32];
    int n = blockIdx.x, c = threadIdx.x;
    const float* p = g_c3 + (size_t)(n*64+c)*36;
    float sum = 0.f, mx = -1e30f;
    #pragma unroll
    for (int s = 0; s < 36; s++) { float v = p[s]; sum += v; mx = fmaxf(mx, v); }
    pm[c] = sum * (1.f/36.f); px[c] = mx;
    __syncthreads();
    if (c < 32) {
        int k = c & 15;
        const float* src = (c < 16) ? pm : px;
        float a = 0.f;
        #pragma unroll
        for (int j = 0; j < 64; j++) a += fc1w[k*64+j]*src[j];
        hsh[c] = fmaxf(a, 0.f);
    }
    __syncthreads();
    float a = 0.f;
    #pragma unroll
    for (int k = 0; k < 16; k++) a += fc2w[c*16+k]*(hsh[k] + hsh[16+k]);
    g_catt[n*64+c] = 1.f/(1.f+expf(-a));
}

// ---------------- CBAM spatial attention + write tokens (N,36,64) ----------------
__global__ void k_spatial(const float* __restrict__ spw) {
    __shared__ float sh[2304], m2[36], x2[36], ss[36];
    int n = blockIdx.x, t = threadIdx.x;
    for (int o = t; o < 2304; o += 256)
        sh[o] = g_c3[(size_t)n*2304 + o] * g_catt[n*64 + o/36];
    __syncthreads();
    if (t < 36) {
        float sum = 0.f, mx = -1e30f;
        #pragma unroll
        for (int c = 0; c < 64; c++) { float v = sh[c*36+t]; sum += v; mx = fmaxf(mx, v); }
        m2[t] = sum*(1.f/64.f); x2[t] = mx;
    }
    __syncthreads();
    if (t < 36) {
        int sy = t/6, sx = t%6;
        float a = 0.f;
        for (int ky = 0; ky < 7; ky++) {
            int iy = sy + ky - 3; if (iy < 0 || iy >= 6) continue;
            for (int kx = 0; kx < 7; kx++) {
                int ix = sx + kx - 3; if (ix < 0 || ix >= 6) continue;
                a += spw[ky*7+kx]*m2[iy*6+ix] + spw[49+ky*7+kx]*x2[iy*6+ix];
            }
        }
        ss[t] = 1.f/(1.f+expf(-a));
    }
    __syncthreads();
    for (int o = t; o < 2304; o += 256) {
        int c = o/36, s = o%36;
        g_tok[((size_t)n*36 + s)*64 + c] = sh[o]*ss[s];
    }
}

// ---------------- generic SGEMM: C(M,N) = act(A(M,K) @ W(N,K)^T + bias) ----------------
// EPI=1: proj epilogue — C is g_h2 in (n, c*36+s) layout, += projb + g_tok residual.
template<int RELU, int BIAS, int EPI>
__global__ void k_gemm(const float* __restrict__ A, const float* __restrict__ W,
                       const float* __restrict__ bias, float* __restrict__ C,
                       int M, int N, int K) {
    __shared__ float As[16][64], Ws[16][64];
    int m0 = blockIdx.x*64, n0 = blockIdx.y*64;
    int tid = threadIdx.x;
    int lr = tid >> 2, lk = (tid & 3) << 2;
    int tx = tid & 15, ty = tid >> 4;
    float acc[4][4] = {};
    for (int k0 = 0; k0 < K; k0 += 16) {
        float4 a = *(const float4*)(A + (size_t)(m0+lr)*K + k0 + lk);
        float4 w = *(const float4*)(W + (size_t)(n0+lr)*K + k0 + lk);
        As[lk  ][lr] = a.x; As[lk+1][lr] = a.y; As[lk+2][lr] = a.z; As[lk+3][lr] = a.w;
        Ws[lk  ][lr] = w.x; Ws[lk+1][lr] = w.y; Ws[lk+2][lr] = w.z; Ws[lk+3][lr] = w.w;
        __syncthreads();
        #pragma unroll
        for (int kk = 0; kk < 16; kk++) {
            float4 av = *(const float4*)&As[kk][tx<<2];
            float4 wv = *(const float4*)&Ws[kk][ty<<2];
            float ar[4] = {av.x, av.y, av.z, av.w};
            float wr[4] = {wv.x, wv.y, wv.z, wv.w};
            #pragma unroll
            for (int i = 0; i < 4; i++)
                #pragma unroll
                for (int j = 0; j < 4; j++)
                    acc[i][j] += ar[i]*wr[j];
        }
        __syncthreads();
    }
    if (EPI) {
        // proj + residual: m -> (img, s); write h2[img*2304 + c*36 + s]
        #pragma unroll
        for (int i = 0; i < 4; i++) {
            int m = m0 + (tx<<2) + i;
            int img = m / 36, s = m % 36;
            float4 tk = *(const float4*)(g_tok + (size_t)m*64 + n0 + (ty<<2));
            float tkv[4] = {tk.x, tk.y, tk.z, tk.w};
            #pragma unroll
            for (int j = 0; j < 4; j++) {
                int c = n0 + (ty<<2) + j;
                C[(size_t)img*2304 + c*36 + s] = acc[i][j] + bias[c] + tkv[j];
            }
        }
        return;
    }
    #pragma unroll
    for (int i = 0; i < 4; i++) {
        int m = m0 + (tx<<2) + i;
        #pragma unroll
        for (int j = 0; j < 4; j++) {
            int nn = n0 + (ty<<2) + j;
            float v = acc[i][j];
            if (BIAS) v += bias[nn];
            if (RELU) v = fmaxf(v, 0.f);
            C[(size_t)m*N + nn] = v;
        }
    }
}

// ---------------- per-(n,head) attention over 36 tokens ----------------
__global__ void k_attn() {
    int head = blockIdx.x, n = blockIdx.y, t = threadIdx.x;
    __shared__ float qs[36*16], ks[36*16], vs[36*16];
    for (int idx = t; idx < 576; idx += 64) {
        int s = idx >> 4, d = idx & 15;
        const float* base = g_qkv + ((size_t)n*36 + s)*192 + head*16 + d;
        qs[idx] = base[0]; ks[idx] = base[64]; vs[idx] = base[128];
    }
    __syncthreads();
    if (t < 36) {
        float qr[16];
        #pragma unroll
        for (int d = 0; d < 16; d++) qr[d] = qs[t*16+d];
        float sc[36]; float mx = -1e30f;
        #pragma unroll
        for (int s2 = 0; s2 < 36; s2++) {
            float a = 0.f;
            #pragma unroll
            for (int d = 0; d < 16; d++) a += qr[d]*ks[s2*16+d];
            a *= 0.25f;
            sc[s2] = a; mx = fmaxf(mx, a);
        }
        float sum = 0.f;
        #pragma unroll
        for (int s2 = 0; s2 < 36; s2++) { float e = expf(sc[s2]-mx); sc[s2] = e; sum += e; }
        float inv = 1.f/sum;
        float o[16];
        #pragma unroll
        for (int d = 0; d < 16; d++) {
            float a = 0.f;
            #pragma unroll
            for (int s2 = 0; s2 < 36; s2++) a += sc[s2]*vs[s2*16+d];
            o[d] = a*inv;
        }
        float* dst = g_attn + ((size_t)n*36 + t)*64 + head*16;
        #pragma unroll
        for (int d4 = 0; d4 < 4; d4++)
            *(float4*)(dst + 4*d4) = make_float4(o[4*d4], o[4*d4+1], o[4*d4+2], o[4*d4+3]);
    }
}

// ---------------- masked GRU scan: 32 independent batch chains ----------------
__global__ void k_gru(const float* __restrict__ done, const float* __restrict__ h0,
                      const float* __restrict__ bhh) {
    int b = blockIdx.x, t = threadIdx.x;
    __shared__ float h_s[128], hm_s[128], gh_s[384];
    h_s[t] = h0[b*128 + t];
    __syncthreads();
    for (int step = 0; step < 64; step++) {
        float dt = done[step*32 + b];
        hm_s[t] = (1.f - dt)*h_s[t];
        __syncthreads();
        if (t < 96) {
            int g = t*4;
            float a0 = bhh[g], a1 = bhh[g+1], a2 = bhh[g+2], a3 = bhh[g+3];
            #pragma unroll 8
            for (int k = 0; k < 128; k++) {
                float hm = hm_s[k];
                float4 w = *(const float4*)(g_whht + k*384 + g);
                a0 += w.x*hm; a1 += w.y*hm; a2 += w.z*hm; a3 += w.w*hm;
            }
            gh_s[g] = a0; gh_s[g+1] = a1; gh_s[g+2] = a2; gh_s[g+3] = a3;
        }
        __syncthreads();
        int row = step*32 + b;
        float xr = g_gx[(size_t)row*384 + t];
        float xz = g_gx[(size_t)row*384 + 128 + t];
        float xn = g_gx[(size_t)row*384 + 256 + t];
        float hr = gh_s[t], hz = gh_s[128+t], hn = gh_s[256+t];
        float rg = 1.f/(1.f+expf(-(xr+hr)));
        float zg = 1.f/(1.f+expf(-(xz+hz)));
        float ng = tanhf(xn + rg*hn);
        float hnew = (1.f-zg)*ng + zg*hm_s[t];
        h_s[t] = hnew;
        g_hid[(size_t)row*128 + t] = hnew;
        __syncthreads();
    }
}

// ---------------- critic head: (2048,128) @ crw^T + crb ----------------
__global__ void k_critic(const float* __restrict__ crw, const float* __restrict__ crb,
                         float* __restrict__ out) {
    int warp = threadIdx.x >> 5, lane = threadIdx.x & 31;
    int row = blockIdx.x*8 + warp;
    const float4* h4 = (const float4*)(g_hid + (size_t)row*128);
    float4 hv = h4[lane];
    float4 wv = ((const float4*)crw)[lane];
    float s = hv.x*wv.x + hv.y*wv.y + hv.z*wv.z + hv.w*wv.w;
    #pragma unroll
    for (int o = 16; o; o >>= 1) s += __shfl_down_sync(0xffffffffu, s, o);
    if (lane == 0) out[row] = s + crb[0];
}

// ---------------- launch ----------------
extern "C" void kernel_launch(void* const* d_in, const int* in_sizes, int n_in,
                              void* d_out, int out_size) {
    const float* x    = (const float*)d_in[0];
    const float* done = (const float*)d_in[1];
    const float* gru0 = (const float*)d_in[2];
    const float* c1w  = (const float*)d_in[3];
    const float* c1b  = (const float*)d_in[4];
    const float* c2w  = (const float*)d_in[5];
    const float* c2b  = (const float*)d_in[6];
    const float* c3w  = (const float*)d_in[7];
    const float* c3b  = (const float*)d_in[8];
    const float* fc1w = (const float*)d_in[9];
    const float* fc2w = (const float*)d_in[10];
    const float* spw  = (const float*)d_in[11];
    const float* qkvw = (const float*)d_in[12];
    const float* projw= (const float*)d_in[13];
    const float* projb= (const float*)d_in[14];
    const float* fcw  = (const float*)d_in[15];
    const float* fcb  = (const float*)d_in[16];
    const float* wih  = (const float*)d_in[17];
    const float* whh  = (const float*)d_in[18];
    const float* bih  = (const float*)d_in[19];
    const float* bhh  = (const float*)d_in[20];
    const float* crw  = (const float*)d_in[21];
    const float* crb  = (const float*)d_in[22];
    float* out = (float*)d_out;

    float *p_tok, *p_qkv, *p_h2, *p_feat, *p_gx, *p_attn;
    cudaGetSymbolAddress((void**)&p_tok,  g_tok);
    cudaGetSymbolAddress((void**)&p_qkv,  g_qkv);
    cudaGetSymbolAddress((void**)&p_h2,   g_h2);
    cudaGetSymbolAddress((void**)&p_feat, g_feat);
    cudaGetSymbolAddress((void**)&p_gx,   g_gx);
    cudaGetSymbolAddress((void**)&p_attn, g_attn);

    // prep (3 launches before conv1 so the profiled launch stays on k_conv1)
    k_transpose<<<(32*256 + 255)/256, 256>>>(c1w, 32, 256, 0);
    k_transpose<<<(64*512 + 255)/256, 256>>>(c2w, 64, 512, 1);
    k_transpose<<<(384*128 + 255)/256, 256>>>(whh, 384, 128, 3);

    // conv backbone
    k_conv1<<<dim3(7, 2048), 128>>>(x, c1b);
    k_transpose<<<(64*576 + 255)/256, 256>>>(c3w, 64, 576, 2);
    k_conv2<<<dim3(13, 512), 128>>>(c2b);
    k_conv3<<<2048, 288>>>(c3b);

    // CBAM
    k_chatt<<<2048, 64>>>(fc1w, fc2w);
    k_spatial<<<2048, 256>>>(spw);

    // spatial self-attention
    k_gemm<0,0,0><<<dim3(73728/64, 192/64), 256>>>(p_tok, qkvw, (const float*)0, p_qkv, 73728, 192, 64);
    k_attn<<<dim3(4, 2048), 64>>>();
    // proj as GEMM with fused residual+transpose epilogue -> g_h2
    k_gemm<0,0,1><<<dim3(73728/64, 1), 256>>>(p_attn, projw, projb, p_h2, 73728, 64, 64);

    // FC + GRU input gates
    k_gemm<1,1,0><<<dim3(2048/64, 256/64), 256>>>(p_h2, fcw, fcb, p_feat, 2048, 256, 2304);
    k_gemm<0,1,0><<<dim3(2048/64, 384/64), 256>>>(p_feat, wih, bih, p_gx, 2048, 384, 256);

    // GRU scan + critic
    k_gru<<<32, 128>>>(done, gru0, bhh);
    k_critic<<<2048/8, 256>>>(crw, crb, out);
}

// round 9
// speedup vs baseline: 1.5174x; 1.1413x over previous
#include <cuda_runtime.h>
#include <math.h>

// ---------------- scratch (device globals; no mallocs) ----------------
// g_c1 rows padded 28 -> 36 floats so conv2 can do unconditional vector loads.
__device__ __align__(16) float g_c1[2048*32*28*36];   // conv1 out (padded rows)
__device__ __align__(16) float g_c2[2048*64*13*13];   // conv2 out
__device__ __align__(16) float g_c3[2048*64*36];      // conv3 out (N,64,36)
__device__ float g_catt[2048*64];       // channel attention
__device__ __align__(16) float g_tok[2048*36*64];     // tokens (N,36,64)
__device__ __align__(16) float g_qkv[2048*36*192];    // qkv
__device__ __align__(16) float g_attn[2048*36*64];    // attention out (N,36,64)
__device__ __align__(16) float g_h2[2048*2304];       // residual -> FC input
__device__ __align__(16) float g_feat[2048*256];      // FC out
__device__ __align__(16) float g_gx[2048*384];        // input-side GRU gates
__device__ __align__(16) float g_hid[2048*128];       // GRU hidden per step
__device__ __align__(16) float g_w1f[4*32*32*2];      // conv1 B fragments (tf32 bits)
__device__ __align__(16) float g_w2t[512*64];
__device__ __align__(16) float g_w3t[576*64];
__device__ __align__(16) float g_whht[128*384];       // whh transposed [k][gate]

// ---------------- mma helper ----------------
__device__ __forceinline__ void mma_tf32(float* d, const unsigned* a,
                                         unsigned b0, unsigned b1) {
    asm volatile(
        "mma.sync.aligned.m16n8k8.row.col.f32.tf32.tf32.f32 "
        "{%0,%1,%2,%3}, {%4,%5,%6,%7}, {%8,%9}, {%0,%1,%2,%3};"
        : "+f"(d[0]), "+f"(d[1]), "+f"(d[2]), "+f"(d[3])
        : "r"(a[0]), "r"(a[1]), "r"(a[2]), "r"(a[3]), "r"(b0), "r"(b1));
}
__device__ __forceinline__ unsigned to_tf32(float f) {
    unsigned r;
    asm("cvt.rna.tf32.f32 %0, %1;" : "=r"(r) : "f"(f));
    return r;
}

// ---------------- weight prep ----------------
// conv1 B fragments: g_w1f[((j*32 + kstep)*32 + lane)*2 + {0,1}]
// b0 = W[kstep*8 + lane%4][j*8 + lane/4], b1 = same k+4; W[k][co] = c1w[co*256+k]
__global__ void k_packB(const float* __restrict__ w) {
    int i = blockIdx.x*256 + threadIdx.x;
    if (i >= 4096) return;
    int lane = i & 31;
    int kstep = (i >> 5) & 31;
    int j = i >> 10;
    int co = j*8 + (lane >> 2);
    int k0 = kstep*8 + (lane & 3);
    g_w1f[i*2]   = __uint_as_float(to_tf32(w[co*256 + k0]));
    g_w1f[i*2+1] = __uint_as_float(to_tf32(w[co*256 + k0 + 4]));
}
__global__ void k_transpose(const float* __restrict__ w, int Cout, int K, int which) {
    int idx = blockIdx.x*256 + threadIdx.x;
    if (idx >= Cout*K) return;
    int co = idx / K, k = idx % K;
    float* dst = (which==1) ? g_w2t : (which==2) ? g_w3t : g_whht;
    dst[k*Cout + co] = w[idx];
}

// ---------------- conv1 (tensor): (N,4,116,116) -> relu (N,32,28,28pad36) ------
// grid(7, 2048), block 128 (4 warps = 4 oy rows). Warp: 2 overlapping m16 tiles
// (ox 0-15, 12-27) x 4 n8 tiles, K=256 as 32 k8-steps (cin,ky).
// Raw input staged in smem (37KB); A-frag = 4 conflict-free LDS.32 per tile;
// B-frag = 1 coalesced L1-hot LDG.64 per ntile.
__global__ void __launch_bounds__(128) k_conv1t(const float* __restrict__ x,
                                                const float* __restrict__ bias) {
    __shared__ __align__(16) float xs[4*20*116];   // 37120 B
    int n = blockIdx.y, bx = blockIdx.x;
    int tid = threadIdx.x;
    {
        int iy0 = 16*bx;
        for (int i = tid; i < 2320; i += 128) {          // 4 cin x 20 rows x 29 f4
            int cin = i / 580;
            int rem = i - cin*580;
            int row = rem / 29, q = rem - row*29;
            float4 v = *(const float4*)(x + ((size_t)(n*4+cin)*116 + iy0 + row)*116 + 4*q);
            *(float4*)(xs + (cin*20 + row)*116 + 4*q) = v;
        }
    }
    __syncthreads();
    int w = tid >> 5, lane = tid & 31;
    int p = lane >> 2, kx = lane & 3;
    int oy = bx*4 + w;
    float acc[2][4][4] = {};
    #pragma unroll
    for (int cin = 0; cin < 4; cin++) {
        #pragma unroll
        for (int ky = 0; ky < 8; ky++) {
            const float* row = xs + (cin*20 + 4*w + ky)*116;
            int kstep = cin*8 + ky;
            unsigned a[2][4];
            #pragma unroll
            for (int t = 0; t < 2; t++) {
                int base = 48*t + 4*p + kx;
                a[t][0] = to_tf32(row[base]);
                a[t][1] = to_tf32(row[base + 32]);
                a[t][2] = to_tf32(row[base + 4]);
                a[t][3] = to_tf32(row[base + 36]);
            }
            const float* wb = g_w1f + (size_t)kstep*64 + lane*2;
            #pragma unroll
            for (int j = 0; j < 4; j++) {
                float2 b = *(const float2*)(wb + (size_t)j*2048);
                unsigned b0 = __float_as_uint(b.x), b1 = __float_as_uint(b.y);
                mma_tf32(acc[0][j], a[0], b0, b1);
                mma_tf32(acc[1][j], a[1], b0, b1);
            }
        }
    }
    // store: c0,c1 -> (row p, co/co+1); c2,c3 -> (row p+8, co/co+1)
    #pragma unroll
    for (int j = 0; j < 4; j++) {
        int co = j*8 + 2*kx;
        float2 bv = *(const float2*)(bias + co);
        float* outp = g_c1 + ((size_t)(n*32+co)*28 + oy)*36;
        #pragma unroll
        for (int t = 0; t < 2; t++) {
            int ox0 = 12*t + p;           // t=0: 0..7 (store); t=1: 12..19 (store if >=16)
            int ox1 = ox0 + 8;            // t=0: 8..15 (store); t=1: 20..27 (store)
            if (t == 0 || ox0 >= 16) {
                float v0 = acc[t][j][0] + bv.x;
                float v1 = acc[t][j][1] + bv.y;
                outp[ox0]        = v0 > 0.f ? v0 : 0.f;
                outp[1008 + ox0] = v1 > 0.f ? v1 : 0.f;
            }
            {
                float v2 = acc[t][j][2] + bv.x;
                float v3 = acc[t][j][3] + bv.y;
                outp[ox1]        = v2 > 0.f ? v2 : 0.f;
                outp[1008 + ox1] = v3 > 0.f ? v3 : 0.f;
            }
        }
    }
}

// ---------------- conv2: (N,32,28pad36) -> relu (N,64,13,13), k4 s2 ------------
// grid(13, 512), block 128: warp = one (n, oy) pair — zero oy waste.
__global__ void __launch_bounds__(128) k_conv2(const float* __restrict__ bias) {
    int w = threadIdx.x >> 5, lane = threadIdx.x & 31;
    int n  = blockIdx.y*4 + w;
    int oy = blockIdx.x;
    int cq  = lane % 16;
    int oxq = lane / 16;
    float acc[7][4] = {};
    for (int cin = 0; cin < 32; cin++) {
        const float* xin = g_c1 + (size_t)(n*32+cin)*1008 + 2*oy*36 + 14*oxq;
        #pragma unroll
        for (int ky = 0; ky < 4; ky++) {
            const float* xr = xin + ky*36;
            float xv[16];
            #pragma unroll
            for (int u = 0; u < 8; u++) {
                float2 v = *(const float2*)(xr + 2*u);
                xv[2*u]=v.x; xv[2*u+1]=v.y;
            }
            const float* wp = g_w2t + ((cin*4+ky)*4)*64 + 4*cq;
            #pragma unroll
            for (int kx = 0; kx < 4; kx++) {
                float4 wv = *(const float4*)(wp + kx*64);
                #pragma unroll
                for (int i = 0; i < 7; i++) {
                    float iv = xv[2*i+kx];
                    acc[i][0] += iv*wv.x; acc[i][1] += iv*wv.y;
                    acc[i][2] += iv*wv.z; acc[i][3] += iv*wv.w;
                }
            }
        }
    }
    #pragma unroll
    for (int j = 0; j < 4; j++) {
        int co = cq*4 + j;
        float b = bias[co];
        #pragma unroll
        for (int i = 0; i < 7; i++) {
            int ox = 7*oxq + i;
            if (ox < 13) {
                float v = acc[i][j] + b;
                g_c2[((size_t)(n*64+co)*13 + oy)*13 + ox] = v > 0.f ? v : 0.f;
            }
        }
    }
}

// ---------------- conv3: (N,64,13,13) -> relu (N,64,6,6), k3 s2 ----------------
__global__ void k_conv3(const float* __restrict__ bias) {
    __shared__ float xs[64*169];   // 43.3 KB
    int n = blockIdx.x;
    int t = threadIdx.x;
    {
        const float4* src = (const float4*)(g_c2 + (size_t)n*10816);
        float4* dst = (float4*)xs;
        for (int i = t; i < 2704; i += 288) dst[i] = src[i];
    }
    __syncthreads();
    int sq = t % 18, cq = t / 18;
    int s0 = sq*2;
    int sy = s0/6, sx = s0%6;
    float acc[2][4] = {};
    for (int cin = 0; cin < 64; cin++) {
        const float* xc = xs + cin*169;
        #pragma unroll
        for (int ky = 0; ky < 3; ky++) {
            const float* row = xc + (2*sy+ky)*13 + 2*sx;
            #pragma unroll
            for (int kx = 0; kx < 3; kx++) {
                float4 wv = *(const float4*)(g_w3t + ((cin*3+ky)*3+kx)*64 + 4*cq);
                float i0 = row[kx];
                float i1 = row[kx+2];
                acc[0][0] += i0*wv.x; acc[0][1] += i0*wv.y;
                acc[0][2] += i0*wv.z; acc[0][3] += i0*wv.w;
                acc[1][0] += i1*wv.x; acc[1][1] += i1*wv.y;
                acc[1][2] += i1*wv.z; acc[1][3] += i1*wv.w;
            }
        }
    }
    #pragma unroll
    for (int j = 0; j < 4; j++) {
        int co = cq*4 + j;
        float b = bias[co];
        #pragma unroll
        for (int i = 0; i < 2; i++) {
            float v = acc[i][j] + b;
            g_c3[(size_t)(n*64+co)*36 + s0 + i] = v > 0.f ? v : 0.f;
        }
    }
}

// ---------------- CBAM channel attention ----------------
__global__ void k_chatt(const float* __restrict__ fc1w, const float* __restrict__ fc2w) {
    __shared__ float pm[64], px[64], hsh[32];
    int n = blockIdx.x, c = threadIdx.x;
    const float* p = g_c3 + (size_t)(n*64+c)*36;
    float sum = 0.f, mx = -1e30f;
    #pragma unroll
    for (int s = 0; s < 36; s++) { float v = p[s]; sum += v; mx = fmaxf(mx, v); }
    pm[c] = sum * (1.f/36.f); px[c] = mx;
    __syncthreads();
    if (c < 32) {
        int k = c & 15;
        const float* src = (c < 16) ? pm : px;
        float a = 0.f;
        #pragma unroll
        for (int j = 0; j < 64; j++) a += fc1w[k*64+j]*src[j];
        hsh[c] = fmaxf(a, 0.f);
    }
    __syncthreads();
    float a = 0.f;
    #pragma unroll
    for (int k = 0; k < 16; k++) a += fc2w[c*16+k]*(hsh[k] + hsh[16+k]);
    g_catt[n*64+c] = 1.f/(1.f+expf(-a));
}

// ---------------- CBAM spatial attention + write tokens (N,36,64) ----------------
__global__ void k_spatial(const float* __restrict__ spw) {
    __shared__ float sh[2304], m2[36], x2[36], ss[36];
    int n = blockIdx.x, t = threadIdx.x;
    for (int o = t; o < 2304; o += 256)
        sh[o] = g_c3[(size_t)n*2304 + o] * g_catt[n*64 + o/36];
    __syncthreads();
    if (t < 36) {
        float sum = 0.f, mx = -1e30f;
        #pragma unroll
        for (int c = 0; c < 64; c++) { float v = sh[c*36+t]; sum += v; mx = fmaxf(mx, v); }
        m2[t] = sum*(1.f/64.f); x2[t] = mx;
    }
    __syncthreads();
    if (t < 36) {
        int sy = t/6, sx = t%6;
        float a = 0.f;
        for (int ky = 0; ky < 7; ky++) {
            int iy = sy + ky - 3; if (iy < 0 || iy >= 6) continue;
            for (int kx = 0; kx < 7; kx++) {
                int ix = sx + kx - 3; if (ix < 0 || ix >= 6) continue;
                a += spw[ky*7+kx]*m2[iy*6+ix] + spw[49+ky*7+kx]*x2[iy*6+ix];
            }
        }
        ss[t] = 1.f/(1.f+expf(-a));
    }
    __syncthreads();
    for (int o = t; o < 2304; o += 256) {
        int c = o/36, s = o%36;
        g_tok[((size_t)n*36 + s)*64 + c] = sh[o]*ss[s];
    }
}

// ---------------- generic SGEMM: C(M,N) = act(A(M,K) @ W(N,K)^T + bias) ----------------
// EPI=1: proj epilogue — C is g_h2 in (n, c*36+s) layout, += projb + g_tok residual.
template<int RELU, int BIAS, int EPI>
__global__ void k_gemm(const float* __restrict__ A, const float* __restrict__ W,
                       const float* __restrict__ bias, float* __restrict__ C,
                       int M, int N, int K) {
    __shared__ float As[16][64], Ws[16][64];
    int m0 = blockIdx.x*64, n0 = blockIdx.y*64;
    int tid = threadIdx.x;
    int lr = tid >> 2, lk = (tid & 3) << 2;
    int tx = tid & 15, ty = tid >> 4;
    float acc[4][4] = {};
    for (int k0 = 0; k0 < K; k0 += 16) {
        float4 a = *(const float4*)(A + (size_t)(m0+lr)*K + k0 + lk);
        float4 w = *(const float4*)(W + (size_t)(n0+lr)*K + k0 + lk);
        As[lk  ][lr] = a.x; As[lk+1][lr] = a.y; As[lk+2][lr] = a.z; As[lk+3][lr] = a.w;
        Ws[lk  ][lr] = w.x; Ws[lk+1][lr] = w.y; Ws[lk+2][lr] = w.z; Ws[lk+3][lr] = w.w;
        __syncthreads();
        #pragma unroll
        for (int kk = 0; kk < 16; kk++) {
            float4 av = *(const float4*)&As[kk][tx<<2];
            float4 wv = *(const float4*)&Ws[kk][ty<<2];
            float ar[4] = {av.x, av.y, av.z, av.w};
            float wr[4] = {wv.x, wv.y, wv.z, wv.w};
            #pragma unroll
            for (int i = 0; i < 4; i++)
                #pragma unroll
                for (int j = 0; j < 4; j++)
                    acc[i][j] += ar[i]*wr[j];
        }
        __syncthreads();
    }
    if (EPI) {
        #pragma unroll
        for (int i = 0; i < 4; i++) {
            int m = m0 + (tx<<2) + i;
            int img = m / 36, s = m % 36;
            float4 tk = *(const float4*)(g_tok + (size_t)m*64 + n0 + (ty<<2));
            float tkv[4] = {tk.x, tk.y, tk.z, tk.w};
            #pragma unroll
            for (int j = 0; j < 4; j++) {
                int c = n0 + (ty<<2) + j;
                C[(size_t)img*2304 + c*36 + s] = acc[i][j] + bias[c] + tkv[j];
            }
        }
        return;
    }
    #pragma unroll
    for (int i = 0; i < 4; i++) {
        int m = m0 + (tx<<2) + i;
        #pragma unroll
        for (int j = 0; j < 4; j++) {
            int nn = n0 + (ty<<2) + j;
            float v = acc[i][j];
            if (BIAS) v += bias[nn];
            if (RELU) v = fmaxf(v, 0.f);
            C[(size_t)m*N + nn] = v;
        }
    }
}

// ---------------- per-(n,head) attention over 36 tokens ----------------
__global__ void k_attn() {
    int head = blockIdx.x, n = blockIdx.y, t = threadIdx.x;
    __shared__ float qs[36*16], ks[36*16], vs[36*16];
    for (int idx = t; idx < 576; idx += 64) {
        int s = idx >> 4, d = idx & 15;
        const float* base = g_qkv + ((size_t)n*36 + s)*192 + head*16 + d;
        qs[idx] = base[0]; ks[idx] = base[64]; vs[idx] = base[128];
    }
    __syncthreads();
    if (t < 36) {
        float qr[16];
        #pragma unroll
        for (int d = 0; d < 16; d++) qr[d] = qs[t*16+d];
        float sc[36]; float mx = -1e30f;
        #pragma unroll
        for (int s2 = 0; s2 < 36; s2++) {
            float a = 0.f;
            #pragma unroll
            for (int d = 0; d < 16; d++) a += qr[d]*ks[s2*16+d];
            a *= 0.25f;
            sc[s2] = a; mx = fmaxf(mx, a);
        }
        float sum = 0.f;
        #pragma unroll
        for (int s2 = 0; s2 < 36; s2++) { float e = expf(sc[s2]-mx); sc[s2] = e; sum += e; }
        float inv = 1.f/sum;
        float o[16];
        #pragma unroll
        for (int d = 0; d < 16; d++) {
            float a = 0.f;
            #pragma unroll
            for (int s2 = 0; s2 < 36; s2++) a += sc[s2]*vs[s2*16+d];
            o[d] = a*inv;
        }
        float* dst = g_attn + ((size_t)n*36 + t)*64 + head*16;
        #pragma unroll
        for (int d4 = 0; d4 < 4; d4++)
            *(float4*)(dst + 4*d4) = make_float4(o[4*d4], o[4*d4+1], o[4*d4+2], o[4*d4+3]);
    }
}

// ---------------- masked GRU scan: 32 independent batch chains ----------------
__global__ void k_gru(const float* __restrict__ done, const float* __restrict__ h0,
                      const float* __restrict__ bhh) {
    int b = blockIdx.x, t = threadIdx.x;
    __shared__ float h_s[128], hm_s[128], gh_s[384];
    h_s[t] = h0[b*128 + t];
    __syncthreads();
    for (int step = 0; step < 64; step++) {
        float dt = done[step*32 + b];
        hm_s[t] = (1.f - dt)*h_s[t];
        __syncthreads();
        if (t < 96) {
            int g = t*4;
            float a0 = bhh[g], a1 = bhh[g+1], a2 = bhh[g+2], a3 = bhh[g+3];
            #pragma unroll 8
            for (int k = 0; k < 128; k++) {
                float hm = hm_s[k];
                float4 w = *(const float4*)(g_whht + k*384 + g);
                a0 += w.x*hm; a1 += w.y*hm; a2 += w.z*hm; a3 += w.w*hm;
            }
            gh_s[g] = a0; gh_s[g+1] = a1; gh_s[g+2] = a2; gh_s[g+3] = a3;
        }
        __syncthreads();
        int row = step*32 + b;
        float xr = g_gx[(size_t)row*384 + t];
        float xz = g_gx[(size_t)row*384 + 128 + t];
        float xn = g_gx[(size_t)row*384 + 256 + t];
        float hr = gh_s[t], hz = gh_s[128+t], hn = gh_s[256+t];
        float rg = 1.f/(1.f+expf(-(xr+hr)));
        float zg = 1.f/(1.f+expf(-(xz+hz)));
        float ng = tanhf(xn + rg*hn);
        float hnew = (1.f-zg)*ng + zg*hm_s[t];
        h_s[t] = hnew;
        g_hid[(size_t)row*128 + t] = hnew;
        __syncthreads();
    }
}

// ---------------- critic head: (2048,128) @ crw^T + crb ----------------
__global__ void k_critic(const float* __restrict__ crw, const float* __restrict__ crb,
                         float* __restrict__ out) {
    int warp = threadIdx.x >> 5, lane = threadIdx.x & 31;
    int row = blockIdx.x*8 + warp;
    const float4* h4 = (const float4*)(g_hid + (size_t)row*128);
    float4 hv = h4[lane];
    float4 wv = ((const float4*)crw)[lane];
    float s = hv.x*wv.x + hv.y*wv.y + hv.z*wv.z + hv.w*wv.w;
    #pragma unroll
    for (int o = 16; o; o >>= 1) s += __shfl_down_sync(0xffffffffu, s, o);
    if (lane == 0) out[row] = s + crb[0];
}

// ---------------- launch ----------------
extern "C" void kernel_launch(void* const* d_in, const int* in_sizes, int n_in,
                              void* d_out, int out_size) {
    const float* x    = (const float*)d_in[0];
    const float* done = (const float*)d_in[1];
    const float* gru0 = (const float*)d_in[2];
    const float* c1w  = (const float*)d_in[3];
    const float* c1b  = (const float*)d_in[4];
    const float* c2w  = (const float*)d_in[5];
    const float* c2b  = (const float*)d_in[6];
    const float* c3w  = (const float*)d_in[7];
    const float* c3b  = (const float*)d_in[8];
    const float* fc1w = (const float*)d_in[9];
    const float* fc2w = (const float*)d_in[10];
    const float* spw  = (const float*)d_in[11];
    const float* qkvw = (const float*)d_in[12];
    const float* projw= (const float*)d_in[13];
    const float* projb= (const float*)d_in[14];
    const float* fcw  = (const float*)d_in[15];
    const float* fcb  = (const float*)d_in[16];
    const float* wih  = (const float*)d_in[17];
    const float* whh  = (const float*)d_in[18];
    const float* bih  = (const float*)d_in[19];
    const float* bhh  = (const float*)d_in[20];
    const float* crw  = (const float*)d_in[21];
    const float* crb  = (const float*)d_in[22];
    float* out = (float*)d_out;

    float *p_tok, *p_qkv, *p_h2, *p_feat, *p_gx, *p_attn;
    cudaGetSymbolAddress((void**)&p_tok,  g_tok);
    cudaGetSymbolAddress((void**)&p_qkv,  g_qkv);
    cudaGetSymbolAddress((void**)&p_h2,   g_h2);
    cudaGetSymbolAddress((void**)&p_feat, g_feat);
    cudaGetSymbolAddress((void**)&p_gx,   g_gx);
    cudaGetSymbolAddress((void**)&p_attn, g_attn);

    // prep (3 launches before conv1 so the profiled launch stays on conv1)
    k_packB<<<16, 256>>>(c1w);
    k_transpose<<<(64*512 + 255)/256, 256>>>(c2w, 64, 512, 1);
    k_transpose<<<(384*128 + 255)/256, 256>>>(whh, 384, 128, 3);

    // conv backbone
    k_conv1t<<<dim3(7, 2048), 128>>>(x, c1b);
    k_transpose<<<(64*576 + 255)/256, 256>>>(c3w, 64, 576, 2);
    k_conv2<<<dim3(13, 512), 128>>>(c2b);
    k_conv3<<<2048, 288>>>(c3b);

    // CBAM
    k_chatt<<<2048, 64>>>(fc1w, fc2w);
    k_spatial<<<2048, 256>>>(spw);

    // spatial self-attention
    k_gemm<0,0,0><<<dim3(73728/64, 192/64), 256>>>(p_tok, qkvw, (const float*)0, p_qkv, 73728, 192, 64);
    k_attn<<<dim3(4, 2048), 64>>>();
    k_gemm<0,0,1><<<dim3(73728/64, 1), 256>>>(p_attn, projw, projb, p_h2, 73728, 64, 64);

    // FC + GRU input gates
    k_gemm<1,1,0><<<dim3(2048/64, 256/64), 256>>>(p_h2, fcw, fcb, p_feat, 2048, 256, 2304);
    k_gemm<0,1,0><<<dim3(2048/64, 384/64), 256>>>(p_feat, wih, bih, p_gx, 2048, 384, 256);

    // GRU scan + critic
    k_gru<<<32, 128>>>(done, gru0, bhh);
    k_critic<<<2048/8, 256>>>(crw, crb, out);
}

// round 10
// speedup vs baseline: 1.7755x; 1.1701x over previous
#include <cuda_runtime.h>
#include <math.h>

// ---------------- scratch (device globals; no mallocs) ----------------
// g_c1 rows padded 28 -> 36 floats; pad stays .bss-zero -> guard-free tensor loads.
__device__ __align__(16) float g_c1[2048*32*28*36];   // conv1 out (padded rows)
__device__ __align__(16) float g_c2[2048*64*13*13];   // conv2 out
__device__ __align__(16) float g_c3[2048*64*36];      // conv3 out (N,64,36)
__device__ float g_catt[2048*64];       // channel attention
__device__ __align__(16) float g_tok[2048*36*64];     // tokens (N,36,64)
__device__ __align__(16) float g_qkv[2048*36*192];    // qkv
__device__ __align__(16) float g_attn[2048*36*64];    // attention out (N,36,64)
__device__ __align__(16) float g_h2[2048*2304];       // residual -> FC input
__device__ __align__(16) float g_feat[2048*256];      // FC out
__device__ __align__(16) float g_gx[2048*384];        // input-side GRU gates
__device__ __align__(16) float g_hid[2048*128];       // GRU hidden per step
__device__ __align__(16) float g_w1f[4*32*32*2];      // conv1 B fragments (tf32 bits)
__device__ __align__(16) float g_w2f[8*64*32*2];      // conv2 B fragments (tf32 bits)
__device__ __align__(16) float g_w3t[576*64];
__device__ __align__(16) float g_whht[128*384];       // whh transposed [k][gate]

// ---------------- mma helpers ----------------
__device__ __forceinline__ void mma_tf32(float* d, const unsigned* a,
                                         unsigned b0, unsigned b1) {
    asm volatile(
        "mma.sync.aligned.m16n8k8.row.col.f32.tf32.tf32.f32 "
        "{%0,%1,%2,%3}, {%4,%5,%6,%7}, {%8,%9}, {%0,%1,%2,%3};"
        : "+f"(d[0]), "+f"(d[1]), "+f"(d[2]), "+f"(d[3])
        : "r"(a[0]), "r"(a[1]), "r"(a[2]), "r"(a[3]), "r"(b0), "r"(b1));
}
__device__ __forceinline__ unsigned to_tf32(float f) {
    unsigned r;
    asm("cvt.rna.tf32.f32 %0, %1;" : "=r"(r) : "f"(f));
    return r;
}

// ---------------- weight prep ----------------
// conv1 B fragments: g_w1f[((j*32 + kstep)*32 + lane)*2 + {0,1}]
__global__ void k_packB(const float* __restrict__ w) {
    int i = blockIdx.x*256 + threadIdx.x;
    if (i >= 4096) return;
    int lane = i & 31;
    int kstep = (i >> 5) & 31;
    int j = i >> 10;
    int co = j*8 + (lane >> 2);
    int k0 = kstep*8 + (lane & 3);
    g_w1f[i*2]   = __uint_as_float(to_tf32(w[co*256 + k0]));
    g_w1f[i*2+1] = __uint_as_float(to_tf32(w[co*256 + k0 + 4]));
}
// conv2 B fragments: kstep = cin*2+s (64 steps); k-local 0-3 = (ky=2s,kx), 4-7 = (ky=2s+1,kx)
// g_w2f[((j*64 + kstep)*32 + lane)*2 + {0,1}]; c2w idx = co*512 + cin*16 + ky*4 + kx
__global__ void k_packB2(const float* __restrict__ w) {
    int i = blockIdx.x*256 + threadIdx.x;
    if (i >= 16384) return;
    int lane = i & 31;
    int kstep = (i >> 5) & 63;
    int j = i >> 11;
    int co = j*8 + (lane >> 2);
    int q  = lane & 3;
    int cin = kstep >> 1, s = kstep & 1;
    int base = co*512 + cin*16 + (2*s)*4 + q;
    g_w2f[i*2]   = __uint_as_float(to_tf32(w[base]));
    g_w2f[i*2+1] = __uint_as_float(to_tf32(w[base + 4]));
}
__global__ void k_transpose(const float* __restrict__ w, int Cout, int K, int which) {
    int idx = blockIdx.x*256 + threadIdx.x;
    if (idx >= Cout*K) return;
    int co = idx / K, k = idx % K;
    float* dst = (which==2) ? g_w3t : g_whht;
    dst[k*Cout + co] = w[idx];
}

// ---------------- conv1 (tensor): (N,4,116,116) -> relu (N,32,28,28pad36) ------
__global__ void __launch_bounds__(128) k_conv1t(const float* __restrict__ x,
                                                const float* __restrict__ bias) {
    __shared__ __align__(16) float xs[4*20*116];   // 37120 B
    int n = blockIdx.y, bx = blockIdx.x;
    int tid = threadIdx.x;
    {
        int iy0 = 16*bx;
        for (int i = tid; i < 2320; i += 128) {
            int cin = i / 580;
            int rem = i - cin*580;
            int row = rem / 29, q = rem - row*29;
            float4 v = *(const float4*)(x + ((size_t)(n*4+cin)*116 + iy0 + row)*116 + 4*q);
            *(float4*)(xs + (cin*20 + row)*116 + 4*q) = v;
        }
    }
    __syncthreads();
    int w = tid >> 5, lane = tid & 31;
    int p = lane >> 2, kx = lane & 3;
    int oy = bx*4 + w;
    float acc[2][4][4] = {};
    #pragma unroll
    for (int cin = 0; cin < 4; cin++) {
        #pragma unroll
        for (int ky = 0; ky < 8; ky++) {
            const float* row = xs + (cin*20 + 4*w + ky)*116;
            int kstep = cin*8 + ky;
            unsigned a[2][4];
            #pragma unroll
            for (int t = 0; t < 2; t++) {
                int base = 48*t + 4*p + kx;
                a[t][0] = to_tf32(row[base]);
                a[t][1] = to_tf32(row[base + 32]);
                a[t][2] = to_tf32(row[base + 4]);
                a[t][3] = to_tf32(row[base + 36]);
            }
            const float* wb = g_w1f + (size_t)kstep*64 + lane*2;
            #pragma unroll
            for (int j = 0; j < 4; j++) {
                float2 b = *(const float2*)(wb + (size_t)j*2048);
                unsigned b0 = __float_as_uint(b.x), b1 = __float_as_uint(b.y);
                mma_tf32(acc[0][j], a[0], b0, b1);
                mma_tf32(acc[1][j], a[1], b0, b1);
            }
        }
    }
    #pragma unroll
    for (int j = 0; j < 4; j++) {
        int co = j*8 + 2*kx;
        float2 bv = *(const float2*)(bias + co);
        float* outp = g_c1 + ((size_t)(n*32+co)*28 + oy)*36;
        #pragma unroll
        for (int t = 0; t < 2; t++) {
            int ox0 = 12*t + p;
            int ox1 = ox0 + 8;
            if (t == 0 || ox0 >= 16) {
                float v0 = acc[t][j][0] + bv.x;
                float v1 = acc[t][j][1] + bv.y;
                outp[ox0]        = v0 > 0.f ? v0 : 0.f;
                outp[1008 + ox0] = v1 > 0.f ? v1 : 0.f;
            }
            {
                float v2 = acc[t][j][2] + bv.x;
                float v3 = acc[t][j][3] + bv.y;
                outp[ox1]        = v2 > 0.f ? v2 : 0.f;
                outp[1008 + ox1] = v3 > 0.f ? v3 : 0.f;
            }
        }
    }
}

// ---------------- conv2 (tensor): (N,32,28pad36) -> relu (N,64,13,13), k4 s2 ---
// grid(13, 512), block 128: warp = one (n, oy). m16 ox tile (0-15; >=13 padded
// reads hit zero columns, outputs discarded), 8 n8 cout tiles, K=512 as 64
// k8-steps (cin, ky-pair). A direct from g_c1 (L1-hot); B fragments L1-hot.
__global__ void __launch_bounds__(128) k_conv2t(const float* __restrict__ bias) {
    int w = threadIdx.x >> 5, lane = threadIdx.x & 31;
    int n  = blockIdx.y*4 + w;
    int oy = blockIdx.x;
    int p = lane >> 2, q = lane & 3;
    float acc[8][4] = {};
    const float* xbase = g_c1 + (size_t)n*32*1008 + 2*oy*36;
    for (int cin = 0; cin < 32; cin++) {
        const float* xc = xbase + cin*1008;
        #pragma unroll
        for (int s = 0; s < 2; s++) {
            const float* row0 = xc + 2*s*36;     // ky = 2s
            const float* row1 = row0 + 36;       // ky = 2s+1
            unsigned a[4];
            a[0] = to_tf32(row0[2*p + q]);
            a[1] = to_tf32(row0[2*p + 16 + q]);
            a[2] = to_tf32(row1[2*p + q]);
            a[3] = to_tf32(row1[2*p + 16 + q]);
            int kstep = cin*2 + s;
            const float* wb = g_w2f + (size_t)kstep*64 + lane*2;
            #pragma unroll
            for (int j = 0; j < 8; j++) {
                float2 b = *(const float2*)(wb + (size_t)j*4096);
                mma_tf32(acc[j], a, __float_as_uint(b.x), __float_as_uint(b.y));
            }
        }
    }
    bool hi = (p + 8 < 13);
    #pragma unroll
    for (int j = 0; j < 8; j++) {
        int co = j*8 + 2*q;
        float2 bv = *(const float2*)(bias + co);
        float* o0 = g_c2 + ((size_t)(n*64+co)*13 + oy)*13;
        float v0 = acc[j][0] + bv.x;
        float v1 = acc[j][1] + bv.y;
        o0[p]       = v0 > 0.f ? v0 : 0.f;
        o0[169 + p] = v1 > 0.f ? v1 : 0.f;
        if (hi) {
            float v2 = acc[j][2] + bv.x;
            float v3 = acc[j][3] + bv.y;
            o0[p + 8]       = v2 > 0.f ? v2 : 0.f;
            o0[169 + p + 8] = v3 > 0.f ? v3 : 0.f;
        }
    }
}

// ---------------- conv3: (N,64,13,13) -> relu (N,64,6,6), k3 s2 ----------------
__global__ void k_conv3(const float* __restrict__ bias) {
    __shared__ float xs[64*169];   // 43.3 KB
    int n = blockIdx.x;
    int t = threadIdx.x;
    {
        const float4* src = (const float4*)(g_c2 + (size_t)n*10816);
        float4* dst = (float4*)xs;
        for (int i = t; i < 2704; i += 288) dst[i] = src[i];
    }
    __syncthreads();
    int sq = t % 18, cq = t / 18;
    int s0 = sq*2;
    int sy = s0/6, sx = s0%6;
    float acc[2][4] = {};
    for (int cin = 0; cin < 64; cin++) {
        const float* xc = xs + cin*169;
        #pragma unroll
        for (int ky = 0; ky < 3; ky++) {
            const float* row = xc + (2*sy+ky)*13 + 2*sx;
            #pragma unroll
            for (int kx = 0; kx < 3; kx++) {
                float4 wv = *(const float4*)(g_w3t + ((cin*3+ky)*3+kx)*64 + 4*cq);
                float i0 = row[kx];
                float i1 = row[kx+2];
                acc[0][0] += i0*wv.x; acc[0][1] += i0*wv.y;
                acc[0][2] += i0*wv.z; acc[0][3] += i0*wv.w;
                acc[1][0] += i1*wv.x; acc[1][1] += i1*wv.y;
                acc[1][2] += i1*wv.z; acc[1][3] += i1*wv.w;
            }
        }
    }
    #pragma unroll
    for (int j = 0; j < 4; j++) {
        int co = cq*4 + j;
        float b = bias[co];
        #pragma unroll
        for (int i = 0; i < 2; i++) {
            float v = acc[i][j] + b;
            g_c3[(size_t)(n*64+co)*36 + s0 + i] = v > 0.f ? v : 0.f;
        }
    }
}

// ---------------- CBAM channel attention ----------------
__global__ void k_chatt(const float* __restrict__ fc1w, const float* __restrict__ fc2w) {
    __shared__ float pm[64], px[64], hsh[32];
    int n = blockIdx.x, c = threadIdx.x;
    const float* p = g_c3 + (size_t)(n*64+c)*36;
    float sum = 0.f, mx = -1e30f;
    #pragma unroll
    for (int s = 0; s < 36; s++) { float v = p[s]; sum += v; mx = fmaxf(mx, v); }
    pm[c] = sum * (1.f/36.f); px[c] = mx;
    __syncthreads();
    if (c < 32) {
        int k = c & 15;
        const float* src = (c < 16) ? pm : px;
        float a = 0.f;
        #pragma unroll
        for (int j = 0; j < 64; j++) a += fc1w[k*64+j]*src[j];
        hsh[c] = fmaxf(a, 0.f);
    }
    __syncthreads();
    float a = 0.f;
    #pragma unroll
    for (int k = 0; k < 16; k++) a += fc2w[c*16+k]*(hsh[k] + hsh[16+k]);
    g_catt[n*64+c] = 1.f/(1.f+expf(-a));
}

// ---------------- CBAM spatial attention + write tokens (N,36,64) ----------------
__global__ void k_spatial(const float* __restrict__ spw) {
    __shared__ float sh[2304], m2[36], x2[36], ss[36];
    int n = blockIdx.x, t = threadIdx.x;
    for (int o = t; o < 2304; o += 256)
        sh[o] = g_c3[(size_t)n*2304 + o] * g_catt[n*64 + o/36];
    __syncthreads();
    if (t < 36) {
        float sum = 0.f, mx = -1e30f;
        #pragma unroll
        for (int c = 0; c < 64; c++) { float v = sh[c*36+t]; sum += v; mx = fmaxf(mx, v); }
        m2[t] = sum*(1.f/64.f); x2[t] = mx;
    }
    __syncthreads();
    if (t < 36) {
        int sy = t/6, sx = t%6;
        float a = 0.f;
        for (int ky = 0; ky < 7; ky++) {
            int iy = sy + ky - 3; if (iy < 0 || iy >= 6) continue;
            for (int kx = 0; kx < 7; kx++) {
                int ix = sx + kx - 3; if (ix < 0 || ix >= 6) continue;
                a += spw[ky*7+kx]*m2[iy*6+ix] + spw[49+ky*7+kx]*x2[iy*6+ix];
            }
        }
        ss[t] = 1.f/(1.f+expf(-a));
    }
    __syncthreads();
    for (int o = t; o < 2304; o += 256) {
        int c = o/36, s = o%36;
        g_tok[((size_t)n*36 + s)*64 + c] = sh[o]*ss[s];
    }
}

// ---------------- generic SGEMM: C(M,N) = act(A(M,K) @ W(N,K)^T + bias) ----------------
template<int RELU, int BIAS, int EPI>
__global__ void k_gemm(const float* __restrict__ A, const float* __restrict__ W,
                       const float* __restrict__ bias, float* __restrict__ C,
                       int M, int N, int K) {
    __shared__ float As[16][64], Ws[16][64];
    int m0 = blockIdx.x*64, n0 = blockIdx.y*64;
    int tid = threadIdx.x;
    int lr = tid >> 2, lk = (tid & 3) << 2;
    int tx = tid & 15, ty = tid >> 4;
    float acc[4][4] = {};
    for (int k0 = 0; k0 < K; k0 += 16) {
        float4 a = *(const float4*)(A + (size_t)(m0+lr)*K + k0 + lk);
        float4 w = *(const float4*)(W + (size_t)(n0+lr)*K + k0 + lk);
        As[lk  ][lr] = a.x; As[lk+1][lr] = a.y; As[lk+2][lr] = a.z; As[lk+3][lr] = a.w;
        Ws[lk  ][lr] = w.x; Ws[lk+1][lr] = w.y; Ws[lk+2][lr] = w.z; Ws[lk+3][lr] = w.w;
        __syncthreads();
        #pragma unroll
        for (int kk = 0; kk < 16; kk++) {
            float4 av = *(const float4*)&As[kk][tx<<2];
            float4 wv = *(const float4*)&Ws[kk][ty<<2];
            float ar[4] = {av.x, av.y, av.z, av.w};
            float wr[4] = {wv.x, wv.y, wv.z, wv.w};
            #pragma unroll
            for (int i = 0; i < 4; i++)
                #pragma unroll
                for (int j = 0; j < 4; j++)
                    acc[i][j] += ar[i]*wr[j];
        }
        __syncthreads();
    }
    if (EPI) {
        #pragma unroll
        for (int i = 0; i < 4; i++) {
            int m = m0 + (tx<<2) + i;
            int img = m / 36, s = m % 36;
            float4 tk = *(const float4*)(g_tok + (size_t)m*64 + n0 + (ty<<2));
            float tkv[4] = {tk.x, tk.y, tk.z, tk.w};
            #pragma unroll
            for (int j = 0; j < 4; j++) {
                int c = n0 + (ty<<2) + j;
                C[(size_t)img*2304 + c*36 + s] = acc[i][j] + bias[c] + tkv[j];
            }
        }
        return;
    }
    #pragma unroll
    for (int i = 0; i < 4; i++) {
        int m = m0 + (tx<<2) + i;
        #pragma unroll
        for (int j = 0; j < 4; j++) {
            int nn = n0 + (ty<<2) + j;
            float v = acc[i][j];
            if (BIAS) v += bias[nn];
            if (RELU) v = fmaxf(v, 0.f);
            C[(size_t)m*N + nn] = v;
        }
    }
}

// ---------------- per-(n,head) attention over 36 tokens ----------------
__global__ void k_attn() {
    int head = blockIdx.x, n = blockIdx.y, t = threadIdx.x;
    __shared__ float qs[36*16], ks[36*16], vs[36*16];
    for (int idx = t; idx < 576; idx += 64) {
        int s = idx >> 4, d = idx & 15;
        const float* base = g_qkv + ((size_t)n*36 + s)*192 + head*16 + d;
        qs[idx] = base[0]; ks[idx] = base[64]; vs[idx] = base[128];
    }
    __syncthreads();
    if (t < 36) {
        float qr[16];
        #pragma unroll
        for (int d = 0; d < 16; d++) qr[d] = qs[t*16+d];
        float sc[36]; float mx = -1e30f;
        #pragma unroll
        for (int s2 = 0; s2 < 36; s2++) {
            float a = 0.f;
            #pragma unroll
            for (int d = 0; d < 16; d++) a += qr[d]*ks[s2*16+d];
            a *= 0.25f;
            sc[s2] = a; mx = fmaxf(mx, a);
        }
        float sum = 0.f;
        #pragma unroll
        for (int s2 = 0; s2 < 36; s2++) { float e = expf(sc[s2]-mx); sc[s2] = e; sum += e; }
        float inv = 1.f/sum;
        float o[16];
        #pragma unroll
        for (int d = 0; d < 16; d++) {
            float a = 0.f;
            #pragma unroll
            for (int s2 = 0; s2 < 36; s2++) a += sc[s2]*vs[s2*16+d];
            o[d] = a*inv;
        }
        float* dst = g_attn + ((size_t)n*36 + t)*64 + head*16;
        #pragma unroll
        for (int d4 = 0; d4 < 4; d4++)
            *(float4*)(dst + 4*d4) = make_float4(o[4*d4], o[4*d4+1], o[4*d4+2], o[4*d4+3]);
    }
}

// ---------------- masked GRU scan: 32 independent batch chains ----------------
__global__ void k_gru(const float* __restrict__ done, const float* __restrict__ h0,
                      const float* __restrict__ bhh) {
    int b = blockIdx.x, t = threadIdx.x;
    __shared__ float h_s[128], hm_s[128], gh_s[384];
    h_s[t] = h0[b*128 + t];
    __syncthreads();
    for (int step = 0; step < 64; step++) {
        float dt = done[step*32 + b];
        hm_s[t] = (1.f - dt)*h_s[t];
        __syncthreads();
        if (t < 96) {
            int g = t*4;
            float a0 = bhh[g], a1 = bhh[g+1], a2 = bhh[g+2], a3 = bhh[g+3];
            #pragma unroll 8
            for (int k = 0; k < 128; k++) {
                float hm = hm_s[k];
                float4 w = *(const float4*)(g_whht + k*384 + g);
                a0 += w.x*hm; a1 += w.y*hm; a2 += w.z*hm; a3 += w.w*hm;
            }
            gh_s[g] = a0; gh_s[g+1] = a1; gh_s[g+2] = a2; gh_s[g+3] = a3;
        }
        __syncthreads();
        int row = step*32 + b;
        float xr = g_gx[(size_t)row*384 + t];
        float xz = g_gx[(size_t)row*384 + 128 + t];
        float xn = g_gx[(size_t)row*384 + 256 + t];
        float hr = gh_s[t], hz = gh_s[128+t], hn = gh_s[256+t];
        float rg = 1.f/(1.f+expf(-(xr+hr)));
        float zg = 1.f/(1.f+expf(-(xz+hz)));
        float ng = tanhf(xn + rg*hn);
        float hnew = (1.f-zg)*ng + zg*hm_s[t];
        h_s[t] = hnew;
        g_hid[(size_t)row*128 + t] = hnew;
        __syncthreads();
    }
}

// ---------------- critic head: (2048,128) @ crw^T + crb ----------------
__global__ void k_critic(const float* __restrict__ crw, const float* __restrict__ crb,
                         float* __restrict__ out) {
    int warp = threadIdx.x >> 5, lane = threadIdx.x & 31;
    int row = blockIdx.x*8 + warp;
    const float4* h4 = (const float4*)(g_hid + (size_t)row*128);
    float4 hv = h4[lane];
    float4 wv = ((const float4*)crw)[lane];
    float s = hv.x*wv.x + hv.y*wv.y + hv.z*wv.z + hv.w*wv.w;
    #pragma unroll
    for (int o = 16; o; o >>= 1) s += __shfl_down_sync(0xffffffffu, s, o);
    if (lane == 0) out[row] = s + crb[0];
}

// ---------------- launch ----------------
extern "C" void kernel_launch(void* const* d_in, const int* in_sizes, int n_in,
                              void* d_out, int out_size) {
    const float* x    = (const float*)d_in[0];
    const float* done = (const float*)d_in[1];
    const float* gru0 = (const float*)d_in[2];
    const float* c1w  = (const float*)d_in[3];
    const float* c1b  = (const float*)d_in[4];
    const float* c2w  = (const float*)d_in[5];
    const float* c2b  = (const float*)d_in[6];
    const float* c3w  = (const float*)d_in[7];
    const float* c3b  = (const float*)d_in[8];
    const float* fc1w = (const float*)d_in[9];
    const float* fc2w = (const float*)d_in[10];
    const float* spw  = (const float*)d_in[11];
    const float* qkvw = (const float*)d_in[12];
    const float* projw= (const float*)d_in[13];
    const float* projb= (const float*)d_in[14];
    const float* fcw  = (const float*)d_in[15];
    const float* fcb  = (const float*)d_in[16];
    const float* wih  = (const float*)d_in[17];
    const float* whh  = (const float*)d_in[18];
    const float* bih  = (const float*)d_in[19];
    const float* bhh  = (const float*)d_in[20];
    const float* crw  = (const float*)d_in[21];
    const float* crb  = (const float*)d_in[22];
    float* out = (float*)d_out;

    float *p_tok, *p_qkv, *p_h2, *p_feat, *p_gx, *p_attn;
    cudaGetSymbolAddress((void**)&p_tok,  g_tok);
    cudaGetSymbolAddress((void**)&p_qkv,  g_qkv);
    cudaGetSymbolAddress((void**)&p_h2,   g_h2);
    cudaGetSymbolAddress((void**)&p_feat, g_feat);
    cudaGetSymbolAddress((void**)&p_gx,   g_gx);
    cudaGetSymbolAddress((void**)&p_attn, g_attn);

    // prep (3 launches before conv1t so the profiled launch stays on conv1t)
    k_packB<<<16, 256>>>(c1w);
    k_packB2<<<64, 256>>>(c2w);
    k_transpose<<<(384*128 + 255)/256, 256>>>(whh, 384, 128, 3);

    // conv backbone
    k_conv1t<<<dim3(7, 2048), 128>>>(x, c1b);
    k_transpose<<<(64*576 + 255)/256, 256>>>(c3w, 64, 576, 2);
    k_conv2t<<<dim3(13, 512), 128>>>(c2b);
    k_conv3<<<2048, 288>>>(c3b);

    // CBAM
    k_chatt<<<2048, 64>>>(fc1w, fc2w);
    k_spatial<<<2048, 256>>>(spw);

    // spatial self-attention
    k_gemm<0,0,0><<<dim3(73728/64, 192/64), 256>>>(p_tok, qkvw, (const float*)0, p_qkv, 73728, 192, 64);
    k_attn<<<dim3(4, 2048), 64>>>();
    k_gemm<0,0,1><<<dim3(73728/64, 1), 256>>>(p_attn, projw, projb, p_h2, 73728, 64, 64);

    // FC + GRU input gates
    k_gemm<1,1,0><<<dim3(2048/64, 256/64), 256>>>(p_h2, fcw, fcb, p_feat, 2048, 256, 2304);
    k_gemm<0,1,0><<<dim3(2048/64, 384/64), 256>>>(p_feat, wih, bih, p_gx, 2048, 384, 256);

    // GRU scan + critic
    k_gru<<<32, 128>>>(done, gru0, bhh);
    k_critic<<<2048/8, 256>>>(crw, crb, out);
}

// round 11
// speedup vs baseline: 1.7927x; 1.0097x over previous
#include <cuda_runtime.h>
#include <math.h>

// ---------------- scratch (device globals; no mallocs) ----------------
// g_c1 rows padded 28 -> 36 floats; pad stays .bss-zero -> guard-free tensor loads.
__device__ __align__(16) float g_c1[2048*32*28*36];   // conv1 out (padded rows)
__device__ __align__(16) float g_c2[2048*64*13*13];   // conv2 out
__device__ __align__(16) float g_c3[2048*64*36];      // conv3 out (N,64,36)
__device__ __align__(16) float g_tok[2048*36*64];     // tokens (N,36,64)
__device__ __align__(16) float g_qkv[2048*36*192];    // qkv
__device__ __align__(16) float g_attn[2048*36*64];    // attention out (N,36,64)
__device__ __align__(16) float g_h2[2048*2304];       // residual -> FC input
__device__ __align__(16) float g_feat[2048*256];      // FC out
__device__ __align__(16) float g_gx[2048*384];        // input-side GRU gates
__device__ __align__(16) float g_hid[2048*128];       // GRU hidden per step
__device__ __align__(16) float g_w1f[4*32*32*2];      // conv1 B fragments (tf32 bits)
__device__ __align__(16) float g_w2f[8*64*32*2];      // conv2 B fragments (tf32 bits)
__device__ __align__(16) float g_w3t[576*64];
__device__ __align__(16) float g_whht[128*384];       // whh transposed [k][gate]

// ---------------- mma helpers ----------------
__device__ __forceinline__ void mma_tf32(float* d, const unsigned* a,
                                         unsigned b0, unsigned b1) {
    asm volatile(
        "mma.sync.aligned.m16n8k8.row.col.f32.tf32.tf32.f32 "
        "{%0,%1,%2,%3}, {%4,%5,%6,%7}, {%8,%9}, {%0,%1,%2,%3};"
        : "+f"(d[0]), "+f"(d[1]), "+f"(d[2]), "+f"(d[3])
        : "r"(a[0]), "r"(a[1]), "r"(a[2]), "r"(a[3]), "r"(b0), "r"(b1));
}
__device__ __forceinline__ unsigned to_tf32(float f) {
    unsigned r;
    asm("cvt.rna.tf32.f32 %0, %1;" : "=r"(r) : "f"(f));
    return r;
}

// ---------------- weight prep ----------------
__global__ void k_packB(const float* __restrict__ w) {
    int i = blockIdx.x*256 + threadIdx.x;
    if (i >= 4096) return;
    int lane = i & 31;
    int kstep = (i >> 5) & 31;
    int j = i >> 10;
    int co = j*8 + (lane >> 2);
    int k0 = kstep*8 + (lane & 3);
    g_w1f[i*2]   = __uint_as_float(to_tf32(w[co*256 + k0]));
    g_w1f[i*2+1] = __uint_as_float(to_tf32(w[co*256 + k0 + 4]));
}
__global__ void k_packB2(const float* __restrict__ w) {
    int i = blockIdx.x*256 + threadIdx.x;
    if (i >= 16384) return;
    int lane = i & 31;
    int kstep = (i >> 5) & 63;
    int j = i >> 11;
    int co = j*8 + (lane >> 2);
    int q  = lane & 3;
    int cin = kstep >> 1, s = kstep & 1;
    int base = co*512 + cin*16 + (2*s)*4 + q;
    g_w2f[i*2]   = __uint_as_float(to_tf32(w[base]));
    g_w2f[i*2+1] = __uint_as_float(to_tf32(w[base + 4]));
}
__global__ void k_transpose(const float* __restrict__ w, int Cout, int K, int which) {
    int idx = blockIdx.x*256 + threadIdx.x;
    if (idx >= Cout*K) return;
    int co = idx / K, k = idx % K;
    float* dst = (which==2) ? g_w3t : g_whht;
    dst[k*Cout + co] = w[idx];
}

// ---------------- conv1 (tensor): (N,4,116,116) -> relu (N,32,28,28pad36) ------
__global__ void __launch_bounds__(128) k_conv1t(const float* __restrict__ x,
                                                const float* __restrict__ bias) {
    __shared__ __align__(16) float xs[4*20*116];   // 37120 B
    int n = blockIdx.y, bx = blockIdx.x;
    int tid = threadIdx.x;
    {
        int iy0 = 16*bx;
        for (int i = tid; i < 2320; i += 128) {
            int cin = i / 580;
            int rem = i - cin*580;
            int row = rem / 29, q = rem - row*29;
            float4 v = *(const float4*)(x + ((size_t)(n*4+cin)*116 + iy0 + row)*116 + 4*q);
            *(float4*)(xs + (cin*20 + row)*116 + 4*q) = v;
        }
    }
    __syncthreads();
    int w = tid >> 5, lane = tid & 31;
    int p = lane >> 2, kx = lane & 3;
    int oy = bx*4 + w;
    float acc[2][4][4] = {};
    #pragma unroll
    for (int cin = 0; cin < 4; cin++) {
        #pragma unroll
        for (int ky = 0; ky < 8; ky++) {
            const float* row = xs + (cin*20 + 4*w + ky)*116;
            int kstep = cin*8 + ky;
            unsigned a[2][4];
            #pragma unroll
            for (int t = 0; t < 2; t++) {
                int base = 48*t + 4*p + kx;
                a[t][0] = to_tf32(row[base]);
                a[t][1] = to_tf32(row[base + 32]);
                a[t][2] = to_tf32(row[base + 4]);
                a[t][3] = to_tf32(row[base + 36]);
            }
            const float* wb = g_w1f + (size_t)kstep*64 + lane*2;
            #pragma unroll
            for (int j = 0; j < 4; j++) {
                float2 b = *(const float2*)(wb + (size_t)j*2048);
                unsigned b0 = __float_as_uint(b.x), b1 = __float_as_uint(b.y);
                mma_tf32(acc[0][j], a[0], b0, b1);
                mma_tf32(acc[1][j], a[1], b0, b1);
            }
        }
    }
    #pragma unroll
    for (int j = 0; j < 4; j++) {
        int co = j*8 + 2*kx;
        float2 bv = *(const float2*)(bias + co);
        float* outp = g_c1 + ((size_t)(n*32+co)*28 + oy)*36;
        #pragma unroll
        for (int t = 0; t < 2; t++) {
            int ox0 = 12*t + p;
            int ox1 = ox0 + 8;
            if (t == 0 || ox0 >= 16) {
                float v0 = acc[t][j][0] + bv.x;
                float v1 = acc[t][j][1] + bv.y;
                outp[ox0]        = v0 > 0.f ? v0 : 0.f;
                outp[1008 + ox0] = v1 > 0.f ? v1 : 0.f;
            }
            {
                float v2 = acc[t][j][2] + bv.x;
                float v3 = acc[t][j][3] + bv.y;
                outp[ox1]        = v2 > 0.f ? v2 : 0.f;
                outp[1008 + ox1] = v3 > 0.f ? v3 : 0.f;
            }
        }
    }
}

// ---------------- conv2 (tensor): (N,32,28pad36) -> relu (N,64,13,13), k4 s2 ---
__global__ void __launch_bounds__(128) k_conv2t(const float* __restrict__ bias) {
    int w = threadIdx.x >> 5, lane = threadIdx.x & 31;
    int n  = blockIdx.y*4 + w;
    int oy = blockIdx.x;
    int p = lane >> 2, q = lane & 3;
    float acc[8][4] = {};
    const float* xbase = g_c1 + (size_t)n*32*1008 + 2*oy*36;
    for (int cin = 0; cin < 32; cin++) {
        const float* xc = xbase + cin*1008;
        #pragma unroll
        for (int s = 0; s < 2; s++) {
            const float* row0 = xc + 2*s*36;
            const float* row1 = row0 + 36;
            unsigned a[4];
            a[0] = to_tf32(row0[2*p + q]);
            a[1] = to_tf32(row0[2*p + 16 + q]);
            a[2] = to_tf32(row1[2*p + q]);
            a[3] = to_tf32(row1[2*p + 16 + q]);
            int kstep = cin*2 + s;
            const float* wb = g_w2f + (size_t)kstep*64 + lane*2;
            #pragma unroll
            for (int j = 0; j < 8; j++) {
                float2 b = *(const float2*)(wb + (size_t)j*4096);
                mma_tf32(acc[j], a, __float_as_uint(b.x), __float_as_uint(b.y));
            }
        }
    }
    bool hi = (p + 8 < 13);
    #pragma unroll
    for (int j = 0; j < 8; j++) {
        int co = j*8 + 2*q;
        float2 bv = *(const float2*)(bias + co);
        float* o0 = g_c2 + ((size_t)(n*64+co)*13 + oy)*13;
        float v0 = acc[j][0] + bv.x;
        float v1 = acc[j][1] + bv.y;
        o0[p]       = v0 > 0.f ? v0 : 0.f;
        o0[169 + p] = v1 > 0.f ? v1 : 0.f;
        if (hi) {
            float v2 = acc[j][2] + bv.x;
            float v3 = acc[j][3] + bv.y;
            o0[p + 8]       = v2 > 0.f ? v2 : 0.f;
            o0[169 + p + 8] = v3 > 0.f ? v3 : 0.f;
        }
    }
}

// ---------------- conv3: (N,64,13,13) -> relu (N,64,6,6), k3 s2 ----------------
__global__ void k_conv3(const float* __restrict__ bias) {
    __shared__ float xs[64*169];   // 43.3 KB
    int n = blockIdx.x;
    int t = threadIdx.x;
    {
        const float4* src = (const float4*)(g_c2 + (size_t)n*10816);
        float4* dst = (float4*)xs;
        for (int i = t; i < 2704; i += 288) dst[i] = src[i];
    }
    __syncthreads();
    int sq = t % 18, cq = t / 18;
    int s0 = sq*2;
    int sy = s0/6, sx = s0%6;
    float acc[2][4] = {};
    for (int cin = 0; cin < 64; cin++) {
        const float* xc = xs + cin*169;
        #pragma unroll
        for (int ky = 0; ky < 3; ky++) {
            const float* row = xc + (2*sy+ky)*13 + 2*sx;
            #pragma unroll
            for (int kx = 0; kx < 3; kx++) {
                float4 wv = *(const float4*)(g_w3t + ((cin*3+ky)*3+kx)*64 + 4*cq);
                float i0 = row[kx];
                float i1 = row[kx+2];
                acc[0][0] += i0*wv.x; acc[0][1] += i0*wv.y;
                acc[0][2] += i0*wv.z; acc[0][3] += i0*wv.w;
                acc[1][0] += i1*wv.x; acc[1][1] += i1*wv.y;
                acc[1][2] += i1*wv.z; acc[1][3] += i1*wv.w;
            }
        }
    }
    #pragma unroll
    for (int j = 0; j < 4; j++) {
        int co = cq*4 + j;
        float b = bias[co];
        #pragma unroll
        for (int i = 0; i < 2; i++) {
            float v = acc[i][j] + b;
            g_c3[(size_t)(n*64+co)*36 + s0 + i] = v > 0.f ? v : 0.f;
        }
    }
}

// ---------------- fused CBAM (channel + spatial) -> tokens (N,36,64) ----------
// block = 1 image, 256 threads. One read of g_c3, all stats in smem, one write.
__global__ void __launch_bounds__(256) k_cbam(const float* __restrict__ fc1w,
                                              const float* __restrict__ fc2w,
                                              const float* __restrict__ spw) {
    __shared__ float sh[2304], pm[64], px[64], hsh[32], ca[64], m2[36], x2[36], ss[36];
    int n = blockIdx.x, t = threadIdx.x;
    for (int o = t; o < 2304; o += 256) sh[o] = g_c3[(size_t)n*2304 + o];
    __syncthreads();
    if (t < 64) {
        const float* p = sh + t*36;
        float sum = 0.f, mx = -1e30f;
        #pragma unroll
        for (int s = 0; s < 36; s++) { float v = p[s]; sum += v; mx = fmaxf(mx, v); }
        pm[t] = sum * (1.f/36.f); px[t] = mx;
    }
    __syncthreads();
    if (t < 32) {
        int k = t & 15;
        const float* src = (t < 16) ? pm : px;
        float a = 0.f;
        #pragma unroll
        for (int j = 0; j < 64; j++) a += fc1w[k*64+j]*src[j];
        hsh[t] = fmaxf(a, 0.f);
    }
    __syncthreads();
    if (t < 64) {
        float a = 0.f;
        #pragma unroll
        for (int k = 0; k < 16; k++) a += fc2w[t*16+k]*(hsh[k] + hsh[16+k]);
        ca[t] = 1.f/(1.f+expf(-a));
    }
    __syncthreads();
    for (int o = t; o < 2304; o += 256) sh[o] *= ca[o/36];
    __syncthreads();
    if (t < 36) {
        float sum = 0.f, mx = -1e30f;
        #pragma unroll
        for (int c = 0; c < 64; c++) { float v = sh[c*36+t]; sum += v; mx = fmaxf(mx, v); }
        m2[t] = sum*(1.f/64.f); x2[t] = mx;
    }
    __syncthreads();
    if (t < 36) {
        int sy = t/6, sx = t%6;
        float a = 0.f;
        for (int ky = 0; ky < 7; ky++) {
            int iy = sy + ky - 3; if (iy < 0 || iy >= 6) continue;
            for (int kx = 0; kx < 7; kx++) {
                int ix = sx + kx - 3; if (ix < 0 || ix >= 6) continue;
                a += spw[ky*7+kx]*m2[iy*6+ix] + spw[49+ky*7+kx]*x2[iy*6+ix];
            }
        }
        ss[t] = 1.f/(1.f+expf(-a));
    }
    __syncthreads();
    for (int o = t; o < 2304; o += 256) {
        int c = o/36, s = o%36;
        g_tok[((size_t)n*36 + s)*64 + c] = sh[o]*ss[s];
    }
}

// ---------------- generic SGEMM: C(M,N) = act(A(M,K) @ W(N,K)^T + bias) ----------------
template<int RELU, int BIAS, int EPI>
__global__ void k_gemm(const float* __restrict__ A, const float* __restrict__ W,
                       const float* __restrict__ bias, float* __restrict__ C,
                       int M, int N, int K) {
    __shared__ float As[16][64], Ws[16][64];
    int m0 = blockIdx.x*64, n0 = blockIdx.y*64;
    int tid = threadIdx.x;
    int lr = tid >> 2, lk = (tid & 3) << 2;
    int tx = tid & 15, ty = tid >> 4;
    float acc[4][4] = {};
    for (int k0 = 0; k0 < K; k0 += 16) {
        float4 a = *(const float4*)(A + (size_t)(m0+lr)*K + k0 + lk);
        float4 w = *(const float4*)(W + (size_t)(n0+lr)*K + k0 + lk);
        As[lk  ][lr] = a.x; As[lk+1][lr] = a.y; As[lk+2][lr] = a.z; As[lk+3][lr] = a.w;
        Ws[lk  ][lr] = w.x; Ws[lk+1][lr] = w.y; Ws[lk+2][lr] = w.z; Ws[lk+3][lr] = w.w;
        __syncthreads();
        #pragma unroll
        for (int kk = 0; kk < 16; kk++) {
            float4 av = *(const float4*)&As[kk][tx<<2];
            float4 wv = *(const float4*)&Ws[kk][ty<<2];
            float ar[4] = {av.x, av.y, av.z, av.w};
            float wr[4] = {wv.x, wv.y, wv.z, wv.w};
            #pragma unroll
            for (int i = 0; i < 4; i++)
                #pragma unroll
                for (int j = 0; j < 4; j++)
                    acc[i][j] += ar[i]*wr[j];
        }
        __syncthreads();
    }
    if (EPI) {
        #pragma unroll
        for (int i = 0; i < 4; i++) {
            int m = m0 + (tx<<2) + i;
            int img = m / 36, s = m % 36;
            float4 tk = *(const float4*)(g_tok + (size_t)m*64 + n0 + (ty<<2));
            float tkv[4] = {tk.x, tk.y, tk.z, tk.w};
            #pragma unroll
            for (int j = 0; j < 4; j++) {
                int c = n0 + (ty<<2) + j;
                C[(size_t)img*2304 + c*36 + s] = acc[i][j] + bias[c] + tkv[j];
            }
        }
        return;
    }
    #pragma unroll
    for (int i = 0; i < 4; i++) {
        int m = m0 + (tx<<2) + i;
        #pragma unroll
        for (int j = 0; j < 4; j++) {
            int nn = n0 + (ty<<2) + j;
            float v = acc[i][j];
            if (BIAS) v += bias[nn];
            if (RELU) v = fmaxf(v, 0.f);
            C[(size_t)m*N + nn] = v;
        }
    }
}

// ---------------- attention: block = 2 images, 288 threads (img,head,tok) -----
// k/v staged in smem (36 KB); q loaded straight to registers. All threads active.
__global__ void __launch_bounds__(288) k_attn() {
    __shared__ float ks[2][36][64], vs[2][36][64];
    int t = threadIdx.x;
    int n0 = blockIdx.x*2;
    for (int i = t; i < 2304; i += 288) {
        int img = i / 1152, rem = i - img*1152;
        int s = rem >> 5, q4 = rem & 31;
        float4 v = *(const float4*)(g_qkv + ((size_t)(n0+img)*36 + s)*192 + 64 + 4*q4);
        if (q4 < 16) *(float4*)&ks[img][s][4*q4] = v;
        else         *(float4*)&vs[img][s][4*(q4-16)] = v;
    }
    __syncthreads();
    int img = t / 144, r = t - img*144;
    int head = r / 36, tok = r - head*36;
    int n = n0 + img;
    float qr[16];
    {
        const float* qp = g_qkv + ((size_t)n*36 + tok)*192 + head*16;
        #pragma unroll
        for (int d4 = 0; d4 < 4; d4++) {
            float4 v = *(const float4*)(qp + 4*d4);
            qr[4*d4] = v.x; qr[4*d4+1] = v.y; qr[4*d4+2] = v.z; qr[4*d4+3] = v.w;
        }
    }
    float sc[36]; float mx = -1e30f;
    #pragma unroll
    for (int s2 = 0; s2 < 36; s2++) {
        const float* kp = &ks[img][s2][head*16];
        float a = 0.f;
        #pragma unroll
        for (int d = 0; d < 16; d++) a += qr[d]*kp[d];
        a *= 0.25f;
        sc[s2] = a; mx = fmaxf(mx, a);
    }
    float sum = 0.f;
    #pragma unroll
    for (int s2 = 0; s2 < 36; s2++) { float e = expf(sc[s2]-mx); sc[s2] = e; sum += e; }
    float inv = 1.f/sum;
    float o[16];
    #pragma unroll
    for (int d = 0; d < 16; d++) {
        float a = 0.f;
        #pragma unroll
        for (int s2 = 0; s2 < 36; s2++) a += sc[s2]*vs[img][s2][head*16+d];
        o[d] = a*inv;
    }
    float* dst = g_attn + ((size_t)n*36 + tok)*64 + head*16;
    #pragma unroll
    for (int d4 = 0; d4 < 4; d4++)
        *(float4*)(dst + 4*d4) = make_float4(o[4*d4], o[4*d4+1], o[4*d4+2], o[4*d4+3]);
}

// ---------------- masked GRU scan: 32 independent batch chains ----------------
__global__ void k_gru(const float* __restrict__ done, const float* __restrict__ h0,
                      const float* __restrict__ bhh) {
    int b = blockIdx.x, t = threadIdx.x;
    __shared__ float h_s[128], hm_s[128], gh_s[384];
    h_s[t] = h0[b*128 + t];
    __syncthreads();
    for (int step = 0; step < 64; step++) {
        float dt = done[step*32 + b];
        hm_s[t] = (1.f - dt)*h_s[t];
        __syncthreads();
        if (t < 96) {
            int g = t*4;
            float a0 = bhh[g], a1 = bhh[g+1], a2 = bhh[g+2], a3 = bhh[g+3];
            #pragma unroll 8
            for (int k = 0; k < 128; k++) {
                float hm = hm_s[k];
                float4 w = *(const float4*)(g_whht + k*384 + g);
                a0 += w.x*hm; a1 += w.y*hm; a2 += w.z*hm; a3 += w.w*hm;
            }
            gh_s[g] = a0; gh_s[g+1] = a1; gh_s[g+2] = a2; gh_s[g+3] = a3;
        }
        __syncthreads();
        int row = step*32 + b;
        float xr = g_gx[(size_t)row*384 + t];
        float xz = g_gx[(size_t)row*384 + 128 + t];
        float xn = g_gx[(size_t)row*384 + 256 + t];
        float hr = gh_s[t], hz = gh_s[128+t], hn = gh_s[256+t];
        float rg = 1.f/(1.f+expf(-(xr+hr)));
        float zg = 1.f/(1.f+expf(-(xz+hz)));
        float ng = tanhf(xn + rg*hn);
        float hnew = (1.f-zg)*ng + zg*hm_s[t];
        h_s[t] = hnew;
        g_hid[(size_t)row*128 + t] = hnew;
        __syncthreads();
    }
}

// ---------------- critic head: (2048,128) @ crw^T + crb ----------------
__global__ void k_critic(const float* __restrict__ crw, const float* __restrict__ crb,
                         float* __restrict__ out) {
    int warp = threadIdx.x >> 5, lane = threadIdx.x & 31;
    int row = blockIdx.x*8 + warp;
    const float4* h4 = (const float4*)(g_hid + (size_t)row*128);
    float4 hv = h4[lane];
    float4 wv = ((const float4*)crw)[lane];
    float s = hv.x*wv.x + hv.y*wv.y + hv.z*wv.z + hv.w*wv.w;
    #pragma unroll
    for (int o = 16; o; o >>= 1) s += __shfl_down_sync(0xffffffffu, s, o);
    if (lane == 0) out[row] = s + crb[0];
}

// ---------------- launch ----------------
extern "C" void kernel_launch(void* const* d_in, const int* in_sizes, int n_in,
                              void* d_out, int out_size) {
    const float* x    = (const float*)d_in[0];
    const float* done = (const float*)d_in[1];
    const float* gru0 = (const float*)d_in[2];
    const float* c1w  = (const float*)d_in[3];
    const float* c1b  = (const float*)d_in[4];
    const float* c2w  = (const float*)d_in[5];
    const float* c2b  = (const float*)d_in[6];
    const float* c3w  = (const float*)d_in[7];
    const float* c3b  = (const float*)d_in[8];
    const float* fc1w = (const float*)d_in[9];
    const float* fc2w = (const float*)d_in[10];
    const float* spw  = (const float*)d_in[11];
    const float* qkvw = (const float*)d_in[12];
    const float* projw= (const float*)d_in[13];
    const float* projb= (const float*)d_in[14];
    const float* fcw  = (const float*)d_in[15];
    const float* fcb  = (const float*)d_in[16];
    const float* wih  = (const float*)d_in[17];
    const float* whh  = (const float*)d_in[18];
    const float* bih  = (const float*)d_in[19];
    const float* bhh  = (const float*)d_in[20];
    const float* crw  = (const float*)d_in[21];
    const float* crb  = (const float*)d_in[22];
    float* out = (float*)d_out;

    float *p_tok, *p_qkv, *p_h2, *p_feat, *p_gx, *p_attn;
    cudaGetSymbolAddress((void**)&p_tok,  g_tok);
    cudaGetSymbolAddress((void**)&p_qkv,  g_qkv);
    cudaGetSymbolAddress((void**)&p_h2,   g_h2);
    cudaGetSymbolAddress((void**)&p_feat, g_feat);
    cudaGetSymbolAddress((void**)&p_gx,   g_gx);
    cudaGetSymbolAddress((void**)&p_attn, g_attn);

    // launch order puts k_conv2t in the profiled slot (#4)
    k_packB<<<16, 256>>>(c1w);
    k_packB2<<<64, 256>>>(c2w);
    k_conv1t<<<dim3(7, 2048), 128>>>(x, c1b);
    k_conv2t<<<dim3(13, 512), 128>>>(c2b);

    k_transpose<<<(64*576 + 255)/256, 256>>>(c3w, 64, 576, 2);
    k_transpose<<<(384*128 + 255)/256, 256>>>(whh, 384, 128, 3);
    k_conv3<<<2048, 288>>>(c3b);

    // fused CBAM
    k_cbam<<<2048, 256>>>(fc1w, fc2w, spw);

    // spatial self-attention
    k_gemm<0,0,0><<<dim3(73728/64, 192/64), 256>>>(p_tok, qkvw, (const float*)0, p_qkv, 73728, 192, 64);
    k_attn<<<1024, 288>>>();
    k_gemm<0,0,1><<<dim3(73728/64, 1), 256>>>(p_attn, projw, projb, p_h2, 73728, 64, 64);

    // FC + GRU input gates
    k_gemm<1,1,0><<<dim3(2048/64, 256/64), 256>>>(p_h2, fcw, fcb, p_feat, 2048, 256, 2304);
    k_gemm<0,1,0><<<dim3(2048/64, 384/64), 256>>>(p_feat, wih, bih, p_gx, 2048, 384, 256);

    // GRU scan + critic
    k_gru<<<32, 128>>>(done, gru0, bhh);
    k_critic<<<2048/8, 256>>>(crw, crb, out);
}

// round 12
// speedup vs baseline: 1.8261x; 1.0186x over previous
#include <cuda_runtime.h>
#include <math.h>

// ---------------- scratch (device globals; no mallocs) ----------------
__device__ __align__(16) float g_c1[2048*32*28*36];   // conv1 out (padded rows)
__device__ __align__(16) float g_c2[2048*64*13*13];   // conv2 out
__device__ __align__(16) float g_c3[2048*64*36];      // conv3 out (N,64,36)
__device__ __align__(16) float g_tok[2048*36*64];     // tokens (N,36,64)
__device__ __align__(16) float g_qkv[2048*36*192];    // qkv
__device__ __align__(16) float g_attn[2048*36*64];    // attention out (N,36,64)
__device__ __align__(16) float g_h2[2048*2304];       // residual -> FC input
__device__ __align__(16) float g_feat[2048*256];      // FC out
__device__ __align__(16) float g_gx[2048*384];        // input-side GRU gates
__device__ __align__(16) float g_hid[2048*128];       // GRU hidden per step
__device__ __align__(16) float g_w1f[4*32*32*2];      // conv1 B fragments (tf32 bits)
__device__ __align__(16) float g_w2f[8*64*32*2];      // conv2 B fragments (tf32 bits)
__device__ __align__(16) float g_w3t[576*64];
__device__ __align__(16) float g_whht[128*384];       // whh transposed [k][gate]

// ---------------- mma helpers ----------------
__device__ __forceinline__ void mma_tf32(float* d, const unsigned* a,
                                         unsigned b0, unsigned b1) {
    asm volatile(
        "mma.sync.aligned.m16n8k8.row.col.f32.tf32.tf32.f32 "
        "{%0,%1,%2,%3}, {%4,%5,%6,%7}, {%8,%9}, {%0,%1,%2,%3};"
        : "+f"(d[0]), "+f"(d[1]), "+f"(d[2]), "+f"(d[3])
        : "r"(a[0]), "r"(a[1]), "r"(a[2]), "r"(a[3]), "r"(b0), "r"(b1));
}
__device__ __forceinline__ unsigned to_tf32(float f) {
    unsigned r;
    asm("cvt.rna.tf32.f32 %0, %1;" : "=r"(r) : "f"(f));
    return r;
}

// ---------------- weight prep ----------------
__global__ void k_packB(const float* __restrict__ w) {
    int i = blockIdx.x*256 + threadIdx.x;
    if (i >= 4096) return;
    int lane = i & 31;
    int kstep = (i >> 5) & 31;
    int j = i >> 10;
    int co = j*8 + (lane >> 2);
    int k0 = kstep*8 + (lane & 3);
    g_w1f[i*2]   = __uint_as_float(to_tf32(w[co*256 + k0]));
    g_w1f[i*2+1] = __uint_as_float(to_tf32(w[co*256 + k0 + 4]));
}
__global__ void k_packB2(const float* __restrict__ w) {
    int i = blockIdx.x*256 + threadIdx.x;
    if (i >= 16384) return;
    int lane = i & 31;
    int kstep = (i >> 5) & 63;
    int j = i >> 11;
    int co = j*8 + (lane >> 2);
    int q  = lane & 3;
    int cin = kstep >> 1, s = kstep & 1;
    int base = co*512 + cin*16 + (2*s)*4 + q;
    g_w2f[i*2]   = __uint_as_float(to_tf32(w[base]));
    g_w2f[i*2+1] = __uint_as_float(to_tf32(w[base + 4]));
}
__global__ void k_transpose(const float* __restrict__ w, int Cout, int K, int which) {
    int idx = blockIdx.x*256 + threadIdx.x;
    if (idx >= Cout*K) return;
    int co = idx / K, k = idx % K;
    float* dst = (which==2) ? g_w3t : g_whht;
    dst[k*Cout + co] = w[idx];
}

// ---------------- conv1 (tensor): (N,4,116,116) -> relu (N,32,28,28pad36) ------
__global__ void __launch_bounds__(128) k_conv1t(const float* __restrict__ x,
                                                const float* __restrict__ bias) {
    __shared__ __align__(16) float xs[4*20*116];   // 37120 B
    int n = blockIdx.y, bx = blockIdx.x;
    int tid = threadIdx.x;
    {
        int iy0 = 16*bx;
        for (int i = tid; i < 2320; i += 128) {
            int cin = i / 580;
            int rem = i - cin*580;
            int row = rem / 29, q = rem - row*29;
            float4 v = *(const float4*)(x + ((size_t)(n*4+cin)*116 + iy0 + row)*116 + 4*q);
            *(float4*)(xs + (cin*20 + row)*116 + 4*q) = v;
        }
    }
    __syncthreads();
    int w = tid >> 5, lane = tid & 31;
    int p = lane >> 2, kx = lane & 3;
    int oy = bx*4 + w;
    float acc[2][4][4] = {};
    #pragma unroll
    for (int cin = 0; cin < 4; cin++) {
        #pragma unroll
        for (int ky = 0; ky < 8; ky++) {
            const float* row = xs + (cin*20 + 4*w + ky)*116;
            int kstep = cin*8 + ky;
            unsigned a[2][4];
            #pragma unroll
            for (int t = 0; t < 2; t++) {
                int base = 48*t + 4*p + kx;
                a[t][0] = to_tf32(row[base]);
                a[t][1] = to_tf32(row[base + 32]);
                a[t][2] = to_tf32(row[base + 4]);
                a[t][3] = to_tf32(row[base + 36]);
            }
            const float* wb = g_w1f + (size_t)kstep*64 + lane*2;
            #pragma unroll
            for (int j = 0; j < 4; j++) {
                float2 b = *(const float2*)(wb + (size_t)j*2048);
                unsigned b0 = __float_as_uint(b.x), b1 = __float_as_uint(b.y);
                mma_tf32(acc[0][j], a[0], b0, b1);
                mma_tf32(acc[1][j], a[1], b0, b1);
            }
        }
    }
    #pragma unroll
    for (int j = 0; j < 4; j++) {
        int co = j*8 + 2*kx;
        float2 bv = *(const float2*)(bias + co);
        float* outp = g_c1 + ((size_t)(n*32+co)*28 + oy)*36;
        #pragma unroll
        for (int t = 0; t < 2; t++) {
            int ox0 = 12*t + p;
            int ox1 = ox0 + 8;
            if (t == 0 || ox0 >= 16) {
                float v0 = acc[t][j][0] + bv.x;
                float v1 = acc[t][j][1] + bv.y;
                outp[ox0]        = v0 > 0.f ? v0 : 0.f;
                outp[1008 + ox0] = v1 > 0.f ? v1 : 0.f;
            }
            {
                float v2 = acc[t][j][2] + bv.x;
                float v3 = acc[t][j][3] + bv.y;
                outp[ox1]        = v2 > 0.f ? v2 : 0.f;
                outp[1008 + ox1] = v3 > 0.f ? v3 : 0.f;
            }
        }
    }
}

// ---------------- conv2 (tensor): (N,32,28pad36) -> relu (N,64,13,13), k4 s2 ---
// unroll 4 on cin -> ~48 loads in flight per warp (was ~12): hides L1/L2 latency.
__global__ void __launch_bounds__(128) k_conv2t(const float* __restrict__ bias) {
    int w = threadIdx.x >> 5, lane = threadIdx.x & 31;
    int n  = blockIdx.y*4 + w;
    int oy = blockIdx.x;
    int p = lane >> 2, q = lane & 3;
    float acc[8][4] = {};
    const float* xbase = g_c1 + (size_t)n*32*1008 + 2*oy*36;
    #pragma unroll 4
    for (int cin = 0; cin < 32; cin++) {
        const float* xc = xbase + cin*1008;
        #pragma unroll
        for (int s = 0; s < 2; s++) {
            const float* row0 = xc + 2*s*36;
            const float* row1 = row0 + 36;
            unsigned a[4];
            a[0] = to_tf32(row0[2*p + q]);
            a[1] = to_tf32(row0[2*p + 16 + q]);
            a[2] = to_tf32(row1[2*p + q]);
            a[3] = to_tf32(row1[2*p + 16 + q]);
            int kstep = cin*2 + s;
            const float* wb = g_w2f + (size_t)kstep*64 + lane*2;
            #pragma unroll
            for (int j = 0; j < 8; j++) {
                float2 b = *(const float2*)(wb + (size_t)j*4096);
                mma_tf32(acc[j], a, __float_as_uint(b.x), __float_as_uint(b.y));
            }
        }
    }
    bool hi = (p + 8 < 13);
    #pragma unroll
    for (int j = 0; j < 8; j++) {
        int co = j*8 + 2*q;
        float2 bv = *(const float2*)(bias + co);
        float* o0 = g_c2 + ((size_t)(n*64+co)*13 + oy)*13;
        float v0 = acc[j][0] + bv.x;
        float v1 = acc[j][1] + bv.y;
        o0[p]       = v0 > 0.f ? v0 : 0.f;
        o0[169 + p] = v1 > 0.f ? v1 : 0.f;
        if (hi) {
            float v2 = acc[j][2] + bv.x;
            float v3 = acc[j][3] + bv.y;
            o0[p + 8]       = v2 > 0.f ? v2 : 0.f;
            o0[169 + p + 8] = v3 > 0.f ? v3 : 0.f;
        }
    }
}

// ---------------- conv3: (N,64,13,13) -> relu (N,64,6,6), k3 s2 ----------------
__global__ void k_conv3(const float* __restrict__ bias) {
    __shared__ float xs[64*169];   // 43.3 KB
    int n = blockIdx.x;
    int t = threadIdx.x;
    {
        const float4* src = (const float4*)(g_c2 + (size_t)n*10816);
        float4* dst = (float4*)xs;
        for (int i = t; i < 2704; i += 288) dst[i] = src[i];
    }
    __syncthreads();
    int sq = t % 18, cq = t / 18;
    int s0 = sq*2;
    int sy = s0/6, sx = s0%6;
    float acc[2][4] = {};
    #pragma unroll 4
    for (int cin = 0; cin < 64; cin++) {
        const float* xc = xs + cin*169;
        #pragma unroll
        for (int ky = 0; ky < 3; ky++) {
            const float* row = xc + (2*sy+ky)*13 + 2*sx;
            #pragma unroll
            for (int kx = 0; kx < 3; kx++) {
                float4 wv = *(const float4*)(g_w3t + ((cin*3+ky)*3+kx)*64 + 4*cq);
                float i0 = row[kx];
                float i1 = row[kx+2];
                acc[0][0] += i0*wv.x; acc[0][1] += i0*wv.y;
                acc[0][2] += i0*wv.z; acc[0][3] += i0*wv.w;
                acc[1][0] += i1*wv.x; acc[1][1] += i1*wv.y;
                acc[1][2] += i1*wv.z; acc[1][3] += i1*wv.w;
            }
        }
    }
    #pragma unroll
    for (int j = 0; j < 4; j++) {
        int co = cq*4 + j;
        float b = bias[co];
        #pragma unroll
        for (int i = 0; i < 2; i++) {
            float v = acc[i][j] + b;
            g_c3[(size_t)(n*64+co)*36 + s0 + i] = v > 0.f ? v : 0.f;
        }
    }
}

// ---------------- fused CBAM (channel + spatial) -> tokens (N,36,64) ----------
__global__ void __launch_bounds__(256) k_cbam(const float* __restrict__ fc1w,
                                              const float* __restrict__ fc2w,
                                              const float* __restrict__ spw) {
    __shared__ float sh[2304], pm[64], px[64], hsh[32], ca[64], m2[36], x2[36], ss[36];
    int n = blockIdx.x, t = threadIdx.x;
    for (int o = t; o < 2304; o += 256) sh[o] = g_c3[(size_t)n*2304 + o];
    __syncthreads();
    if (t < 64) {
        const float* p = sh + t*36;
        float sum = 0.f, mx = -1e30f;
        #pragma unroll
        for (int s = 0; s < 36; s++) { float v = p[s]; sum += v; mx = fmaxf(mx, v); }
        pm[t] = sum * (1.f/36.f); px[t] = mx;
    }
    __syncthreads();
    if (t < 32) {
        int k = t & 15;
        const float* src = (t < 16) ? pm : px;
        float a = 0.f;
        #pragma unroll
        for (int j = 0; j < 64; j++) a += fc1w[k*64+j]*src[j];
        hsh[t] = fmaxf(a, 0.f);
    }
    __syncthreads();
    if (t < 64) {
        float a = 0.f;
        #pragma unroll
        for (int k = 0; k < 16; k++) a += fc2w[t*16+k]*(hsh[k] + hsh[16+k]);
        ca[t] = 1.f/(1.f+expf(-a));
    }
    __syncthreads();
    for (int o = t; o < 2304; o += 256) sh[o] *= ca[o/36];
    __syncthreads();
    if (t < 36) {
        float sum = 0.f, mx = -1e30f;
        #pragma unroll
        for (int c = 0; c < 64; c++) { float v = sh[c*36+t]; sum += v; mx = fmaxf(mx, v); }
        m2[t] = sum*(1.f/64.f); x2[t] = mx;
    }
    __syncthreads();
    if (t < 36) {
        int sy = t/6, sx = t%6;
        float a = 0.f;
        for (int ky = 0; ky < 7; ky++) {
            int iy = sy + ky - 3; if (iy < 0 || iy >= 6) continue;
            for (int kx = 0; kx < 7; kx++) {
                int ix = sx + kx - 3; if (ix < 0 || ix >= 6) continue;
                a += spw[ky*7+kx]*m2[iy*6+ix] + spw[49+ky*7+kx]*x2[iy*6+ix];
            }
        }
        ss[t] = 1.f/(1.f+expf(-a));
    }
    __syncthreads();
    for (int o = t; o < 2304; o += 256) {
        int c = o/36, s = o%36;
        g_tok[((size_t)n*36 + s)*64 + c] = sh[o]*ss[s];
    }
}

// ---------------- SGEMM, double-buffered + register prefetch ----------------
// One __syncthreads per 16-k chunk; next chunk's LDG issued before the FFMA loop.
// EPI=1: proj epilogue — C is g_h2 in (n, c*36+s) layout, += projb + g_tok residual.
template<int RELU, int BIAS, int EPI>
__global__ void k_gemm(const float* __restrict__ A, const float* __restrict__ W,
                       const float* __restrict__ bias, float* __restrict__ C,
                       int M, int N, int K) {
    __shared__ float As[2][16][64], Ws[2][16][64];
    int m0 = blockIdx.x*64, n0 = blockIdx.y*64;
    int tid = threadIdx.x;
    int lr = tid >> 2, lk = (tid & 3) << 2;
    int tx = tid & 15, ty = tid >> 4;
    float acc[4][4] = {};
    // prologue: load + store chunk 0
    float4 a = *(const float4*)(A + (size_t)(m0+lr)*K + lk);
    float4 w = *(const float4*)(W + (size_t)(n0+lr)*K + lk);
    As[0][lk  ][lr] = a.x; As[0][lk+1][lr] = a.y; As[0][lk+2][lr] = a.z; As[0][lk+3][lr] = a.w;
    Ws[0][lk  ][lr] = w.x; Ws[0][lk+1][lr] = w.y; Ws[0][lk+2][lr] = w.z; Ws[0][lk+3][lr] = w.w;
    int nch = K >> 4;
    for (int ch = 0; ch < nch; ch++) {
        __syncthreads();
        int cur = ch & 1;
        bool pf = (ch + 1 < nch);
        if (pf) {
            a = *(const float4*)(A + (size_t)(m0+lr)*K + (ch+1)*16 + lk);
            w = *(const float4*)(W + (size_t)(n0+lr)*K + (ch+1)*16 + lk);
        }
        #pragma unroll
        for (int kk = 0; kk < 16; kk++) {
            float4 av = *(const float4*)&As[cur][kk][tx<<2];
            float4 wv = *(const float4*)&Ws[cur][kk][ty<<2];
            float ar[4] = {av.x, av.y, av.z, av.w};
            float wr[4] = {wv.x, wv.y, wv.z, wv.w};
            #pragma unroll
            for (int i = 0; i < 4; i++)
                #pragma unroll
                for (int j = 0; j < 4; j++)
                    acc[i][j] += ar[i]*wr[j];
        }
        if (pf) {
            int nxt = cur ^ 1;
            As[nxt][lk  ][lr] = a.x; As[nxt][lk+1][lr] = a.y;
            As[nxt][lk+2][lr] = a.z; As[nxt][lk+3][lr] = a.w;
            Ws[nxt][lk  ][lr] = w.x; Ws[nxt][lk+1][lr] = w.y;
            Ws[nxt][lk+2][lr] = w.z; Ws[nxt][lk+3][lr] = w.w;
        }
    }
    if (EPI) {
        #pragma unroll
        for (int i = 0; i < 4; i++) {
            int m = m0 + (tx<<2) + i;
            int img = m / 36, s = m % 36;
            float4 tk = *(const float4*)(g_tok + (size_t)m*64 + n0 + (ty<<2));
            float tkv[4] = {tk.x, tk.y, tk.z, tk.w};
            #pragma unroll
            for (int j = 0; j < 4; j++) {
                int c = n0 + (ty<<2) + j;
                C[(size_t)img*2304 + c*36 + s] = acc[i][j] + bias[c] + tkv[j];
            }
        }
        return;
    }
    #pragma unroll
    for (int i = 0; i < 4; i++) {
        int m = m0 + (tx<<2) + i;
        #pragma unroll
        for (int j = 0; j < 4; j++) {
            int nn = n0 + (ty<<2) + j;
            float v = acc[i][j];
            if (BIAS) v += bias[nn];
            if (RELU) v = fmaxf(v, 0.f);
            C[(size_t)m*N + nn] = v;
        }
    }
}

// ---------------- attention: block = 2 images, 288 threads (img,head,tok) -----
__global__ void __launch_bounds__(288) k_attn() {
    __shared__ float ks[2][36][64], vs[2][36][64];
    int t = threadIdx.x;
    int n0 = blockIdx.x*2;
    for (int i = t; i < 2304; i += 288) {
        int img = i / 1152, rem = i - img*1152;
        int s = rem >> 5, q4 = rem & 31;
        float4 v = *(const float4*)(g_qkv + ((size_t)(n0+img)*36 + s)*192 + 64 + 4*q4);
        if (q4 < 16) *(float4*)&ks[img][s][4*q4] = v;
        else         *(float4*)&vs[img][s][4*(q4-16)] = v;
    }
    __syncthreads();
    int img = t / 144, r = t - img*144;
    int head = r / 36, tok = r - head*36;
    int n = n0 + img;
    float qr[16];
    {
        const float* qp = g_qkv + ((size_t)n*36 + tok)*192 + head*16;
        #pragma unroll
        for (int d4 = 0; d4 < 4; d4++) {
            float4 v = *(const float4*)(qp + 4*d4);
            qr[4*d4] = v.x; qr[4*d4+1] = v.y; qr[4*d4+2] = v.z; qr[4*d4+3] = v.w;
        }
    }
    float sc[36]; float mx = -1e30f;
    #pragma unroll
    for (int s2 = 0; s2 < 36; s2++) {
        const float* kp = &ks[img][s2][head*16];
        float a = 0.f;
        #pragma unroll
        for (int d = 0; d < 16; d++) a += qr[d]*kp[d];
        a *= 0.25f;
        sc[s2] = a; mx = fmaxf(mx, a);
    }
    float sum = 0.f;
    #pragma unroll
    for (int s2 = 0; s2 < 36; s2++) { float e = expf(sc[s2]-mx); sc[s2] = e; sum += e; }
    float inv = 1.f/sum;
    float o[16];
    #pragma unroll
    for (int d = 0; d < 16; d++) {
        float a = 0.f;
        #pragma unroll
        for (int s2 = 0; s2 < 36; s2++) a += sc[s2]*vs[img][s2][head*16+d];
        o[d] = a*inv;
    }
    float* dst = g_attn + ((size_t)n*36 + tok)*64 + head*16;
    #pragma unroll
    for (int d4 = 0; d4 < 4; d4++)
        *(float4*)(dst + 4*d4) = make_float4(o[4*d4], o[4*d4+1], o[4*d4+2], o[4*d4+3]);
}

// ---------------- masked GRU scan: 32 independent batch chains ----------------
__global__ void k_gru(const float* __restrict__ done, const float* __restrict__ h0,
                      const float* __restrict__ bhh) {
    int b = blockIdx.x, t = threadIdx.x;
    __shared__ float h_s[128], hm_s[128], gh_s[384];
    h_s[t] = h0[b*128 + t];
    __syncthreads();
    for (int step = 0; step < 64; step++) {
        float dt = done[step*32 + b];
        hm_s[t] = (1.f - dt)*h_s[t];
        __syncthreads();
        if (t < 96) {
            int g = t*4;
            float a0 = bhh[g], a1 = bhh[g+1], a2 = bhh[g+2], a3 = bhh[g+3];
            #pragma unroll 8
            for (int k = 0; k < 128; k++) {
                float hm = hm_s[k];
                float4 w = *(const float4*)(g_whht + k*384 + g);
                a0 += w.x*hm; a1 += w.y*hm; a2 += w.z*hm; a3 += w.w*hm;
            }
            gh_s[g] = a0; gh_s[g+1] = a1; gh_s[g+2] = a2; gh_s[g+3] = a3;
        }
        __syncthreads();
        int row = step*32 + b;
        float xr = g_gx[(size_t)row*384 + t];
        float xz = g_gx[(size_t)row*384 + 128 + t];
        float xn = g_gx[(size_t)row*384 + 256 + t];
        float hr = gh_s[t], hz = gh_s[128+t], hn = gh_s[256+t];
        float rg = 1.f/(1.f+expf(-(xr+hr)));
        float zg = 1.f/(1.f+expf(-(xz+hz)));
        float ng = tanhf(xn + rg*hn);
        float hnew = (1.f-zg)*ng + zg*hm_s[t];
        h_s[t] = hnew;
        g_hid[(size_t)row*128 + t] = hnew;
        __syncthreads();
    }
}

// ---------------- critic head: (2048,128) @ crw^T + crb ----------------
__global__ void k_critic(const float* __restrict__ crw, const float* __restrict__ crb,
                         float* __restrict__ out) {
    int warp = threadIdx.x >> 5, lane = threadIdx.x & 31;
    int row = blockIdx.x*8 + warp;
    const float4* h4 = (const float4*)(g_hid + (size_t)row*128);
    float4 hv = h4[lane];
    float4 wv = ((const float4*)crw)[lane];
    float s = hv.x*wv.x + hv.y*wv.y + hv.z*wv.z + hv.w*wv.w;
    #pragma unroll
    for (int o = 16; o; o >>= 1) s += __shfl_down_sync(0xffffffffu, s, o);
    if (lane == 0) out[row] = s + crb[0];
}

// ---------------- launch ----------------
extern "C" void kernel_launch(void* const* d_in, const int* in_sizes, int n_in,
                              void* d_out, int out_size) {
    const float* x    = (const float*)d_in[0];
    const float* done = (const float*)d_in[1];
    const float* gru0 = (const float*)d_in[2];
    const float* c1w  = (const float*)d_in[3];
    const float* c1b  = (const float*)d_in[4];
    const float* c2w  = (const float*)d_in[5];
    const float* c2b  = (const float*)d_in[6];
    const float* c3w  = (const float*)d_in[7];
    const float* c3b  = (const float*)d_in[8];
    const float* fc1w = (const float*)d_in[9];
    const float* fc2w = (const float*)d_in[10];
    const float* spw  = (const float*)d_in[11];
    const float* qkvw = (const float*)d_in[12];
    const float* projw= (const float*)d_in[13];
    const float* projb= (const float*)d_in[14];
    const float* fcw  = (const float*)d_in[15];
    const float* fcb  = (const float*)d_in[16];
    const float* wih  = (const float*)d_in[17];
    const float* whh  = (const float*)d_in[18];
    const float* bih  = (const float*)d_in[19];
    const float* bhh  = (const float*)d_in[20];
    const float* crw  = (const float*)d_in[21];
    const float* crb  = (const float*)d_in[22];
    float* out = (float*)d_out;

    float *p_tok, *p_qkv, *p_h2, *p_feat, *p_gx, *p_attn;
    cudaGetSymbolAddress((void**)&p_tok,  g_tok);
    cudaGetSymbolAddress((void**)&p_qkv,  g_qkv);
    cudaGetSymbolAddress((void**)&p_h2,   g_h2);
    cudaGetSymbolAddress((void**)&p_feat, g_feat);
    cudaGetSymbolAddress((void**)&p_gx,   g_gx);
    cudaGetSymbolAddress((void**)&p_attn, g_attn);

    // launch order keeps k_conv2t in the profiled slot (#4)
    k_packB<<<16, 256>>>(c1w);
    k_packB2<<<64, 256>>>(c2w);
    k_conv1t<<<dim3(7, 2048), 128>>>(x, c1b);
    k_conv2t<<<dim3(13, 512), 128>>>(c2b);

    k_transpose<<<(64*576 + 255)/256, 256>>>(c3w, 64, 576, 2);
    k_transpose<<<(384*128 + 255)/256, 256>>>(whh, 384, 128, 3);
    k_conv3<<<2048, 288>>>(c3b);

    // fused CBAM
    k_cbam<<<2048, 256>>>(fc1w, fc2w, spw);

    // spatial self-attention
    k_gemm<0,0,0><<<dim3(73728/64, 192/64), 256>>>(p_tok, qkvw, (const float*)0, p_qkv, 73728, 192, 64);
    k_attn<<<1024, 288>>>();
    k_gemm<0,0,1><<<dim3(73728/64, 1), 256>>>(p_attn, projw, projb, p_h2, 73728, 64, 64);

    // FC + GRU input gates
    k_gemm<1,1,0><<<dim3(2048/64, 256/64), 256>>>(p_h2, fcw, fcb, p_feat, 2048, 256, 2304);
    k_gemm<0,1,0><<<dim3(2048/64, 384/64), 256>>>(p_feat, wih, bih, p_gx, 2048, 384, 256);

    // GRU scan + critic
    k_gru<<<32, 128>>>(done, gru0, bhh);
    k_critic<<<2048/8, 256>>>(crw, crb, out);
}